// round 1
// baseline (speedup 1.0000x reference)
#include <cuda_runtime.h>
#include <math.h>

#define BB   2
#define SS   2048
#define HH   2304
#define NH   8
#define HD   256
#define NKV  4
#define WIN  512
#define MROWS (BB*SS)   // 4096

// Scratch (device globals; no allocation allowed)
__device__ float g_q[BB*NH*SS*HD];     // [B, NH, S, HD]
__device__ float g_k[BB*NKV*SS*HD];    // [B, NKV, S, HD]
__device__ float g_v[BB*NKV*SS*HD];    // [B, NKV, S, HD]
__device__ float g_ao[BB*SS*NH*HD];    // [B*S, NH*HD]

// ---------------------------------------------------------------------------
// Tiled fp32 GEMM: C[M,N] = A[M,K] @ W[K,N]
// mode 0: C row-major [M,N]
// mode 1: C head-major [(b*nheads+h)*SS + s]*HD + d   (m=b*SS+s, n=h*HD+d)
// M,N,K divisible by 64/64/16.
// ---------------------------------------------------------------------------
__global__ __launch_bounds__(256) void gemm_tiled(
    const float* __restrict__ A, const float* __restrict__ W, float* __restrict__ C,
    int M, int N, int K, int mode, int nheads)
{
    __shared__ float As[16][64];
    __shared__ float Bs[16][64];
    const int tid = threadIdx.x;
    const int m0 = blockIdx.y * 64;
    const int n0 = blockIdx.x * 64;
    const int ty = tid >> 4, tx = tid & 15;
    const int arow = tid >> 2, acol = (tid & 3) << 2;
    const int brow = tid >> 4, bcol = (tid & 15) << 2;

    float acc[4][4];
#pragma unroll
    for (int i = 0; i < 4; i++)
#pragma unroll
        for (int j = 0; j < 4; j++) acc[i][j] = 0.f;

    const float* Aptr = A + (size_t)(m0 + arow) * K + acol;
    const float* Wptr = W + (size_t)brow * N + n0 + bcol;

    for (int k0 = 0; k0 < K; k0 += 16) {
        float4 av = *(const float4*)(Aptr + k0);
        As[acol + 0][arow] = av.x;
        As[acol + 1][arow] = av.y;
        As[acol + 2][arow] = av.z;
        As[acol + 3][arow] = av.w;
        *(float4*)&Bs[brow][bcol] = *(const float4*)(Wptr + (size_t)k0 * N);
        __syncthreads();
#pragma unroll
        for (int kk = 0; kk < 16; kk++) {
            float4 a4 = *(const float4*)&As[kk][ty << 2];
            float4 b4 = *(const float4*)&Bs[kk][tx << 2];
            float ar[4] = {a4.x, a4.y, a4.z, a4.w};
            float br[4] = {b4.x, b4.y, b4.z, b4.w};
#pragma unroll
            for (int i = 0; i < 4; i++)
#pragma unroll
                for (int j = 0; j < 4; j++) acc[i][j] += ar[i] * br[j];
        }
        __syncthreads();
    }

    if (mode == 0) {
#pragma unroll
        for (int i = 0; i < 4; i++) {
            int m = m0 + (ty << 2) + i;
            float4 v = make_float4(acc[i][0], acc[i][1], acc[i][2], acc[i][3]);
            *(float4*)&C[(size_t)m * N + n0 + (tx << 2)] = v;
        }
    } else {
        int n = n0 + (tx << 2);
        int hIdx = n / HD;
        int dIdx = n - hIdx * HD;
#pragma unroll
        for (int i = 0; i < 4; i++) {
            int m = m0 + (ty << 2) + i;
            int b = m >> 11;          // m / SS  (SS = 2048)
            int s = m & (SS - 1);
            float4 v = make_float4(acc[i][0], acc[i][1], acc[i][2], acc[i][3]);
            *(float4*)&C[(((size_t)b * nheads + hIdx) * SS + s) * HD + dIdx] = v;
        }
    }
}

// ---------------------------------------------------------------------------
// RoPE in place on head-major [B, heads, S, HD]; pairs (d, d+128)
// ---------------------------------------------------------------------------
__global__ __launch_bounds__(256) void rope_kernel(
    float* __restrict__ X, const int* __restrict__ pos_ids, int heads)
{
    int t = blockIdx.x * blockDim.x + threadIdx.x;
    int d = t & 127;
    int s = (t >> 7) & (SS - 1);
    int rest = t >> 18;              // t / (128*SS)
    int hh = rest % heads;
    int b  = rest / heads;
    if (b >= BB) return;

    float pos = (float)pos_ids[b * SS + s];
    float inv = powf(10000.f, -(float)d * (1.f / 128.f));
    float ang = pos * inv;
    float si, c;
    sincosf(ang, &si, &c);
    size_t base = (((size_t)b * heads + hh) * SS + s) * HD;
    float x1 = X[base + d];
    float x2 = X[base + d + 128];
    X[base + d]       = x1 * c - x2 * si;
    X[base + d + 128] = x2 * c + x1 * si;
}

// ---------------------------------------------------------------------------
// Sliding-window causal attention with tanh softcap, online softmax.
// Block: 32 q rows for one (b, h). 256 threads = 32 rows x 8 d-chunks.
// Thread (r, dc) owns dims {dc + 8*j : j=0..31} of row r.
// Dynamic smem: sK[32][256] + sV[32][256] = 64KB.
// ---------------------------------------------------------------------------
__global__ __launch_bounds__(256) void attn_kernel(
    const float* __restrict__ Q, const float* __restrict__ Kg,
    const float* __restrict__ Vg, float* __restrict__ AO)
{
    extern __shared__ float sm[];
    float* sK = sm;             // 32*256
    float* sV = sm + 32 * 256;  // 32*256
    __shared__ float sS[32][33];

    const int tid = threadIdx.x;
    const int r  = tid >> 3;
    const int dc = tid & 7;
    const int bq = blockIdx.x;
    const int h  = blockIdx.y;
    const int b  = blockIdx.z;
    const int kv = h >> 1;          // NH/NKV = 2
    const int qi = bq * 32 + r;

    float qreg[32], o[32];
    const float* qp = Q + (((size_t)(b * NH + h)) * SS + qi) * HD;
#pragma unroll
    for (int j = 0; j < 32; j++) { qreg[j] = qp[dc + 8 * j]; o[j] = 0.f; }
    float mrow = -1e30f, l = 0.f;

    int kstart = bq * 32 - (WIN - 1);
    if (kstart < 0) kstart = 0;
    int kt0 = kstart & ~31;
    const int kend = bq * 32 + 31;

    const float* kbase = Kg + ((size_t)(b * NKV + kv)) * SS * HD;
    const float* vbase = Vg + ((size_t)(b * NKV + kv)) * SS * HD;

    for (; kt0 <= kend; kt0 += 32) {
        // cooperative load of K,V tiles (float4, coalesced)
#pragma unroll
        for (int i = 0; i < 8; i++) {
            int f4  = i * 256 + tid;       // 0..2047 float4 slots
            int row = f4 >> 6;
            int col = (f4 & 63) << 2;
            *(float4*)&sK[row * 256 + col] =
                *(const float4*)&kbase[(size_t)(kt0 + row) * HD + col];
            *(float4*)&sV[row * 256 + col] =
                *(const float4*)&vbase[(size_t)(kt0 + row) * HD + col];
        }
        __syncthreads();

        // Phase A: scores for 32 keys (partial dots + 8-lane reduce)
        float tmax = -1e30f;
        for (int k = 0; k < 32; k++) {
            float a = 0.f;
            const float* kp = sK + k * 256 + dc;
#pragma unroll
            for (int j = 0; j < 32; j++) a += qreg[j] * kp[8 * j];
            a += __shfl_xor_sync(0xffffffffu, a, 1, 8);
            a += __shfl_xor_sync(0xffffffffu, a, 2, 8);
            a += __shfl_xor_sync(0xffffffffu, a, 4, 8);
            int kj = kt0 + k;
            float s;
            if (kj <= qi && (qi - kj) < WIN)
                s = 50.f * tanhf(a * (1.f / (16.f * 50.f)));
            else
                s = -1e30f;
            if (dc == 0) sS[r][k] = s;
            tmax = fmaxf(tmax, s);
        }
        __syncwarp();

        // Phase B: online softmax update + PV accumulate
        float mnew  = fmaxf(mrow, tmax);
        float alpha = __expf(mrow - mnew);
        l *= alpha;
#pragma unroll
        for (int j = 0; j < 32; j++) o[j] *= alpha;
        for (int k = 0; k < 32; k++) {
            float s = sS[r][k];
            float p = (s > -1e29f) ? __expf(s - mnew) : 0.f;
            l += p;
            const float* vp = sV + k * 256 + dc;
#pragma unroll
            for (int j = 0; j < 32; j++) o[j] += p * vp[8 * j];
        }
        mrow = mnew;
        __syncthreads();
    }

    float invl = 1.f / l;
    float* op = AO + ((size_t)(b * SS + qi)) * (NH * HD) + h * HD;
#pragma unroll
    for (int j = 0; j < 32; j++) op[dc + 8 * j] = o[j] * invl;
}

// ---------------------------------------------------------------------------
extern "C" void kernel_launch(void* const* d_in, const int* in_sizes, int n_in,
                              void* d_out, int out_size)
{
    const float* hid = (const float*)d_in[0];
    // d_in[1] = attention_mask (pure causal; semantics folded into attn kernel)
    const int*   pos = (const int*)d_in[2];
    const float* Wq  = (const float*)d_in[3];
    const float* Wk  = (const float*)d_in[4];
    const float* Wv  = (const float*)d_in[5];
    const float* Wo  = (const float*)d_in[6];
    float* out = (float*)d_out;

    float *qp, *kp, *vp, *aop;
    cudaGetSymbolAddress((void**)&qp,  g_q);
    cudaGetSymbolAddress((void**)&kp,  g_k);
    cudaGetSymbolAddress((void**)&vp,  g_v);
    cudaGetSymbolAddress((void**)&aop, g_ao);

    // QKV projections (head-major epilogue)
    gemm_tiled<<<dim3((NH*HD)/64,  MROWS/64), 256>>>(hid, Wq, qp, MROWS, NH*HD,  HH, 1, NH);
    gemm_tiled<<<dim3((NKV*HD)/64, MROWS/64), 256>>>(hid, Wk, kp, MROWS, NKV*HD, HH, 1, NKV);
    gemm_tiled<<<dim3((NKV*HD)/64, MROWS/64), 256>>>(hid, Wv, vp, MROWS, NKV*HD, HH, 1, NKV);

    // RoPE
    rope_kernel<<<(BB*SS*NH*128)/256, 256>>>(qp, pos, NH);
    rope_kernel<<<(BB*SS*NKV*128)/256, 256>>>(kp, pos, NKV);

    // Attention
    cudaFuncSetAttribute(attn_kernel, cudaFuncAttributeMaxDynamicSharedMemorySize, 64*1024);
    attn_kernel<<<dim3(SS/32, NH, BB), 256, 64*1024>>>(qp, kp, vp, aop);

    // Output projection
    gemm_tiled<<<dim3(HH/64, MROWS/64), 256>>>(aop, Wo, out, MROWS, HH, 2048, 0, 0);
}

// round 3
// speedup vs baseline: 1.9649x; 1.9649x over previous
#include <cuda_runtime.h>
#include <cuda_bf16.h>
#include <cstdint>
#include <math.h>

#define BB   2
#define SS   2048
#define HH   2304
#define NH   8
#define HD   256
#define NKV  4
#define WIN  512
#define MROWS (BB*SS)            // 4096
#define K2QKV (3*HH)             // 6912
#define K2O   (3*2048)           // 6144
#define NQKV  (NH*HD + 2*NKV*HD) // 4096
#define NST   3
#define STAGE_BYTES 32768        // 16KB A + 16KB B per stage
#define GEMM_SMEM (NST*STAGE_BYTES + 1024)

// ------------------------- device scratch (no allocs allowed) ---------------
__device__ float g_q[(size_t)BB*NH*SS*HD];
__device__ float g_k[(size_t)BB*NKV*SS*HD];
__device__ float g_v[(size_t)BB*NKV*SS*HD];
__device__ float g_ao[(size_t)BB*SS*NH*HD];
__device__ __align__(256) __nv_bfloat16 g_a2 [(size_t)MROWS*K2QKV];
__device__ __align__(256) __nv_bfloat16 g_b2 [(size_t)NQKV*K2QKV];
__device__ __align__(256) __nv_bfloat16 g_a2o[(size_t)MROWS*K2O];
__device__ __align__(256) __nv_bfloat16 g_b2o[(size_t)HH*K2O];

// ------------------------- PTX helpers --------------------------------------
__device__ __forceinline__ uint32_t smem_u32(const void* p) {
    uint32_t a;
    asm("{ .reg .u64 t; cvta.to.shared.u64 t, %1; cvt.u32.u64 %0, t; }" : "=r"(a) : "l"(p));
    return a;
}
__device__ __forceinline__ void cp_async16(uint32_t saddr, const void* gaddr) {
    asm volatile("cp.async.cg.shared.global [%0], [%1], 16;" :: "r"(saddr), "l"(gaddr) : "memory");
}
__device__ __forceinline__ void cp_commit() {
    asm volatile("cp.async.commit_group;" ::: "memory");
}
__device__ __forceinline__ void cp_wait2() {
    asm volatile("cp.async.wait_group 2;" ::: "memory");
}
__device__ __forceinline__ void ldsm4(uint32_t* r, uint32_t addr) {
    asm volatile("ldmatrix.sync.aligned.m8n8.x4.shared.b16 {%0,%1,%2,%3}, [%4];"
                 : "=r"(r[0]), "=r"(r[1]), "=r"(r[2]), "=r"(r[3]) : "r"(addr));
}
__device__ __forceinline__ void mma16816(float* c, const uint32_t* a, const uint32_t* b) {
    asm volatile(
        "mma.sync.aligned.m16n8k16.row.col.f32.bf16.bf16.f32 "
        "{%0,%1,%2,%3}, {%4,%5,%6,%7}, {%8,%9}, {%0,%1,%2,%3};"
        : "+f"(c[0]), "+f"(c[1]), "+f"(c[2]), "+f"(c[3])
        : "r"(a[0]), "r"(a[1]), "r"(a[2]), "r"(a[3]), "r"(b[0]), "r"(b[1]));
}
#define SWZ(off) ((off) ^ (((off) >> 3) & 0x70))

// ------------------------- split-bf16 prep kernels --------------------------
// A side: per original k, emit {hi, hi, lo}
__global__ __launch_bounds__(256) void split3_rows(
    const float* __restrict__ X, __nv_bfloat16* __restrict__ Y, int total, int K)
{
    int t = blockIdx.x * blockDim.x + threadIdx.x;
    if (t >= total) return;
    int m = t / K, k = t - m * K;
    float x = X[t];
    __nv_bfloat16 hi = __float2bfloat16(x);
    __nv_bfloat16 lo = __float2bfloat16(x - __bfloat162float(hi));
    size_t o = (size_t)m * (3 * (size_t)K) + 3 * (size_t)k;
    Y[o] = hi; Y[o + 1] = hi; Y[o + 2] = lo;
}
// B side: W[K,N] -> Y[n, 3k+{0,1,2}] = {hi, lo, hi}  (transpose+split)
__global__ __launch_bounds__(256) void split3_transpose(
    const float* __restrict__ W, __nv_bfloat16* __restrict__ Y, int K, int N, int K2)
{
    __shared__ float t[32][33];
    int k0 = blockIdx.y * 32, n0 = blockIdx.x * 32;
    int tx = threadIdx.x & 31, ty = threadIdx.x >> 5; // ty 0..7
#pragma unroll
    for (int i = 0; i < 4; i++)
        t[ty + i * 8][tx] = W[(size_t)(k0 + ty + i * 8) * N + n0 + tx];
    __syncthreads();
#pragma unroll
    for (int i = 0; i < 4; i++) {
        int n = n0 + ty + i * 8;
        int k = k0 + tx;
        float x = t[tx][ty + i * 8];
        __nv_bfloat16 hi = __float2bfloat16(x);
        __nv_bfloat16 lo = __float2bfloat16(x - __bfloat162float(hi));
        size_t o = (size_t)n * K2 + 3 * (size_t)k;
        Y[o] = hi; Y[o + 1] = lo; Y[o + 2] = hi;
    }
}

// ------------------------- HMMA (mma.sync) GEMM -----------------------------
// C[M,N] = A2[M,K2] @ B2[N,K2]^T  (both K-major bf16, fp32 accum)
// Block 128x128, 8 warps (4m x 2n), warp tile 32x64, K-chunk 64.
// mode 0: row-major C (ldN), mode 1: scatter into q/k/v head-major.
__global__ __launch_bounds__(256) void gemm_tc(
    const __nv_bfloat16* __restrict__ A2, const __nv_bfloat16* __restrict__ B2,
    float* __restrict__ Cq, float* __restrict__ Ck, float* __restrict__ Cv,
    int K2, int mode, int ldN)
{
    extern __shared__ char dsm[];
    const int tid = threadIdx.x;
    const int wid = tid >> 5;
    const int lane = tid & 31;
    const int m0 = blockIdx.y * 128;
    const int n0 = blockIdx.x * 128;
    const int warpM = (wid & 3) * 32;
    const int warpN = (wid >> 2) * 64;

    uint32_t raw = smem_u32(dsm);
    uint32_t sbase = (raw + 1023u) & ~1023u;
    char* dtile = dsm + (sbase - raw);

    const int nk = K2 >> 6;              // chunks of 64 bf16
    const int colb = (tid & 7) * 16;     // byte col in 128B row
    const int r0 = tid >> 3;             // 0..31

    float c[2][8][4];
#pragma unroll
    for (int mi = 0; mi < 2; mi++)
#pragma unroll
        for (int nf = 0; nf < 8; nf++)
#pragma unroll
            for (int j = 0; j < 4; j++) c[mi][nf][j] = 0.f;

    // ldmatrix lane addressing (within a 128B-row swizzled tile)
    const int lrow = lane & 15;
    const int lchunk = (lane >> 4) * 16; // 0 or 16 bytes

    // prologue: fill NST stages
#pragma unroll
    for (int s = 0; s < NST; s++) {
        uint32_t sA = sbase + s * STAGE_BYTES;
        uint32_t sB = sA + 16384;
        int k0 = s * 64;
#pragma unroll
        for (int i = 0; i < 4; i++) {
            int row = i * 32 + r0;
            uint32_t so = SWZ((uint32_t)(row * 128 + colb));
            cp_async16(sA + so, A2 + (size_t)(m0 + row) * K2 + k0 + (tid & 7) * 8);
            cp_async16(sB + so, B2 + (size_t)(n0 + row) * K2 + k0 + (tid & 7) * 8);
        }
        cp_commit();
    }

    for (int ck = 0; ck < nk; ck++) {
        const int s = ck - (ck / NST) * NST;
        cp_wait2();
        __syncthreads();

        uint32_t sA = sbase + s * STAGE_BYTES;
        uint32_t sB = sA + 16384;

#pragma unroll
        for (int ks = 0; ks < 4; ks++) {
            const int kb = ks * 32 + lchunk;
            uint32_t a[2][4], b[4][4];
#pragma unroll
            for (int mi = 0; mi < 2; mi++) {
                int row = warpM + mi * 16 + lrow;
                ldsm4(a[mi], sA + SWZ((uint32_t)(row * 128 + kb)));
            }
#pragma unroll
            for (int ni = 0; ni < 4; ni++) {
                int row = warpN + ni * 16 + lrow;
                ldsm4(b[ni], sB + SWZ((uint32_t)(row * 128 + kb)));
            }
#pragma unroll
            for (int mi = 0; mi < 2; mi++)
#pragma unroll
                for (int ni = 0; ni < 4; ni++) {
                    uint32_t blo[2] = { b[ni][0], b[ni][2] };
                    uint32_t bhi[2] = { b[ni][1], b[ni][3] };
                    mma16816(c[mi][2 * ni + 0], a[mi], blo);
                    mma16816(c[mi][2 * ni + 1], a[mi], bhi);
                }
        }
        __syncthreads();

        const int nck = ck + NST;
        if (nck < nk) {
            int k0 = nck * 64;
#pragma unroll
            for (int i = 0; i < 4; i++) {
                int row = i * 32 + r0;
                uint32_t so = SWZ((uint32_t)(row * 128 + colb));
                cp_async16(sA + so, A2 + (size_t)(m0 + row) * K2 + k0 + (tid & 7) * 8);
                cp_async16(sB + so, B2 + (size_t)(n0 + row) * K2 + k0 + (tid & 7) * 8);
            }
        }
        cp_commit();
    }

    // ---- epilogue: accum regs -> smem tile -> coalesced global stores ----
    __syncthreads();  // all mma reads of smem done; reuse smem as float tile
    float* stile = (float*)dtile;    // rows of 132 floats
    {
        int rquad = lane >> 2;
        int cpair = (lane & 3) << 1;
#pragma unroll
        for (int mi = 0; mi < 2; mi++) {
            int rbase = warpM + mi * 16 + rquad;
#pragma unroll
            for (int nf = 0; nf < 8; nf++) {
                int col = warpN + nf * 8 + cpair;
                *(float2*)&stile[rbase * 132 + col]       = make_float2(c[mi][nf][0], c[mi][nf][1]);
                *(float2*)&stile[(rbase + 8) * 132 + col] = make_float2(c[mi][nf][2], c[mi][nf][3]);
            }
        }
    }
    __syncthreads();

    if (mode == 0) {
#pragma unroll
        for (int i = 0; i < 16; i++) {
            int idx = i * 256 + tid;
            int row = idx >> 5, c4 = idx & 31;
            float4 v = *(float4*)&stile[row * 132 + c4 * 4];
            int m = m0 + row;
            *(float4*)&Cq[(size_t)m * ldN + n0 + c4 * 4] = v;
        }
    } else {
        float* tens; int hh, hp;
        if (n0 < 2048)      { tens = Cq; hh = n0 >> 8;          hp = NH; }
        else if (n0 < 3072) { tens = Ck; hh = (n0 - 2048) >> 8; hp = NKV; }
        else                { tens = Cv; hh = (n0 - 3072) >> 8; hp = NKV; }
        int d0 = n0 & 255;
#pragma unroll
        for (int i = 0; i < 16; i++) {
            int idx = i * 256 + tid;
            int row = idx >> 5, c4 = idx & 31;
            float4 v = *(float4*)&stile[row * 132 + c4 * 4];
            int m = m0 + row;
            int b = m >> 11, sq = m & (SS - 1);
            *(float4*)&tens[(((size_t)(b * hp + hh)) * SS + sq) * HD + d0 + c4 * 4] = v;
        }
    }
}

// ------------------------- RoPE ---------------------------------------------
__global__ __launch_bounds__(256) void rope_kernel(
    float* __restrict__ X, const int* __restrict__ pos_ids, int heads)
{
    int t = blockIdx.x * blockDim.x + threadIdx.x;
    int d = t & 127;
    int s = (t >> 7) & (SS - 1);
    int rest = t >> 18;
    int hh = rest % heads;
    int b  = rest / heads;
    if (b >= BB) return;

    float pos = (float)pos_ids[b * SS + s];
    float inv = powf(10000.f, -(float)d * (1.f / 128.f));
    float ang = pos * inv;
    float si, c;
    sincosf(ang, &si, &c);
    size_t base = (((size_t)b * heads + hh) * SS + s) * HD;
    float x1 = X[base + d];
    float x2 = X[base + d + 128];
    X[base + d]       = x1 * c - x2 * si;
    X[base + d + 128] = x2 * c + x1 * si;
}

// ------------------------- attention (fp32) ---------------------------------
__global__ __launch_bounds__(256) void attn_kernel(
    const float* __restrict__ Q, const float* __restrict__ Kg,
    const float* __restrict__ Vg, float* __restrict__ AO)
{
    extern __shared__ float sm[];
    float* sK = sm;
    float* sV = sm + 32 * 256;
    __shared__ float sS[32][33];

    const int tid = threadIdx.x;
    const int r  = tid >> 3;
    const int dc = tid & 7;
    const int bq = blockIdx.x;
    const int h  = blockIdx.y;
    const int b  = blockIdx.z;
    const int kv = h >> 1;
    const int qi = bq * 32 + r;

    float qreg[32], o[32];
    const float* qp = Q + (((size_t)(b * NH + h)) * SS + qi) * HD;
#pragma unroll
    for (int j = 0; j < 32; j++) { qreg[j] = qp[dc + 8 * j]; o[j] = 0.f; }
    float mrow = -1e30f, l = 0.f;

    int kstart = bq * 32 - (WIN - 1);
    if (kstart < 0) kstart = 0;
    int kt0 = kstart & ~31;
    const int kend = bq * 32 + 31;

    const float* kbase = Kg + ((size_t)(b * NKV + kv)) * SS * HD;
    const float* vbase = Vg + ((size_t)(b * NKV + kv)) * SS * HD;

    for (; kt0 <= kend; kt0 += 32) {
#pragma unroll
        for (int i = 0; i < 8; i++) {
            int f4  = i * 256 + tid;
            int row = f4 >> 6;
            int col = (f4 & 63) << 2;
            *(float4*)&sK[row * 256 + col] =
                *(const float4*)&kbase[(size_t)(kt0 + row) * HD + col];
            *(float4*)&sV[row * 256 + col] =
                *(const float4*)&vbase[(size_t)(kt0 + row) * HD + col];
        }
        __syncthreads();

        float tmax = -1e30f;
        for (int k = 0; k < 32; k++) {
            float a = 0.f;
            const float* kp = sK + k * 256 + dc;
#pragma unroll
            for (int j = 0; j < 32; j++) a += qreg[j] * kp[8 * j];
            a += __shfl_xor_sync(0xffffffffu, a, 1, 8);
            a += __shfl_xor_sync(0xffffffffu, a, 2, 8);
            a += __shfl_xor_sync(0xffffffffu, a, 4, 8);
            int kj = kt0 + k;
            float s;
            if (kj <= qi && (qi - kj) < WIN)
                s = 50.f * tanhf(a * (1.f / (16.f * 50.f)));
            else
                s = -1e30f;
            if (dc == 0) sS[r][k] = s;
            tmax = fmaxf(tmax, s);
        }
        __syncwarp();

        float mnew  = fmaxf(mrow, tmax);
        float alpha = __expf(mrow - mnew);
        l *= alpha;
#pragma unroll
        for (int j = 0; j < 32; j++) o[j] *= alpha;
        for (int k = 0; k < 32; k++) {
            float s = sS[r][k];
            float p = (s > -1e29f) ? __expf(s - mnew) : 0.f;
            l += p;
            const float* vp = sV + k * 256 + dc;
#pragma unroll
            for (int j = 0; j < 32; j++) o[j] += p * vp[8 * j];
        }
        mrow = mnew;
        __syncthreads();
    }

    float invl = 1.f / l;
    float* op = AO + ((size_t)(b * SS + qi)) * (NH * HD) + h * HD;
#pragma unroll
    for (int j = 0; j < 32; j++) op[dc + 8 * j] = o[j] * invl;
}

// ---------------------------------------------------------------------------
extern "C" void kernel_launch(void* const* d_in, const int* in_sizes, int n_in,
                              void* d_out, int out_size)
{
    const float* hid = (const float*)d_in[0];
    const int*   pos = (const int*)d_in[2];
    const float* Wq  = (const float*)d_in[3];
    const float* Wk  = (const float*)d_in[4];
    const float* Wv  = (const float*)d_in[5];
    const float* Wo  = (const float*)d_in[6];
    float* out = (float*)d_out;

    float *qp, *kp, *vp, *aop;
    __nv_bfloat16 *a2, *b2, *a2o, *b2o;
    cudaGetSymbolAddress((void**)&qp,  g_q);
    cudaGetSymbolAddress((void**)&kp,  g_k);
    cudaGetSymbolAddress((void**)&vp,  g_v);
    cudaGetSymbolAddress((void**)&aop, g_ao);
    cudaGetSymbolAddress((void**)&a2,  g_a2);
    cudaGetSymbolAddress((void**)&b2,  g_b2);
    cudaGetSymbolAddress((void**)&a2o, g_a2o);
    cudaGetSymbolAddress((void**)&b2o, g_b2o);

    cudaFuncSetAttribute(gemm_tc, cudaFuncAttributeMaxDynamicSharedMemorySize, GEMM_SMEM);
    cudaFuncSetAttribute(attn_kernel, cudaFuncAttributeMaxDynamicSharedMemorySize, 64*1024);

    // ---- QKV: split prep ----
    split3_rows<<<(MROWS*HH + 255)/256, 256>>>(hid, a2, MROWS*HH, HH);
    split3_transpose<<<dim3(2048/32, HH/32), 256>>>(Wq, b2, HH, 2048, K2QKV);
    split3_transpose<<<dim3(1024/32, HH/32), 256>>>(Wk, b2 + (size_t)2048*K2QKV, HH, 1024, K2QKV);
    split3_transpose<<<dim3(1024/32, HH/32), 256>>>(Wv, b2 + (size_t)3072*K2QKV, HH, 1024, K2QKV);

    // ---- fused QKV GEMM on tensor cores ----
    gemm_tc<<<dim3(NQKV/128, MROWS/128), 256, GEMM_SMEM>>>(a2, b2, qp, kp, vp, K2QKV, 1, 0);

    // ---- RoPE ----
    rope_kernel<<<(BB*SS*NH*128)/256, 256>>>(qp, pos, NH);
    rope_kernel<<<(BB*SS*NKV*128)/256, 256>>>(kp, pos, NKV);

    // ---- attention ----
    attn_kernel<<<dim3(SS/32, NH, BB), 256, 64*1024>>>(qp, kp, vp, aop);

    // ---- out projection ----
    split3_rows<<<(MROWS*2048 + 255)/256, 256>>>(aop, a2o, MROWS*2048, 2048);
    split3_transpose<<<dim3(HH/32, 2048/32), 256>>>(Wo, b2o, 2048, HH, K2O);
    gemm_tc<<<dim3(HH/128, MROWS/128), 256, GEMM_SMEM>>>(a2o, b2o, out, nullptr, nullptr, K2O, 0, HH);
}

// round 5
// speedup vs baseline: 3.4806x; 1.7714x over previous
#include <cuda_runtime.h>
#include <cuda_bf16.h>
#include <cuda_fp16.h>
#include <cstdint>
#include <math.h>

#define BB   2
#define SS   2048
#define HH   2304
#define NH   8
#define HD   256
#define NKV  4
#define WIN  512
#define MROWS (BB*SS)            // 4096
#define K2QKV (3*HH)             // 6912
#define K2O   (3*2048)           // 6144
#define NQKV  (NH*HD + 2*NKV*HD) // 4096
#define NST   3
#define STAGE_BYTES 32768
#define GEMM_SMEM (NST*STAGE_BYTES + 1024)
#define ATT_SMEM (5*32768 + 1024)   // Qh Ql Kh Kl Vh tiles (32KB each) + align

// ------------------------- device scratch (no allocs allowed) ---------------
__device__ float g_q[(size_t)BB*NH*SS*HD];
__device__ float g_k[(size_t)BB*NKV*SS*HD];
__device__ float g_v[(size_t)BB*NKV*SS*HD];
__device__ float g_ao[(size_t)BB*SS*NH*HD];
__device__ __align__(256) __nv_bfloat16 g_a2 [(size_t)MROWS*K2QKV];
__device__ __align__(256) __nv_bfloat16 g_b2 [(size_t)NQKV*K2QKV];
__device__ __align__(256) __nv_bfloat16 g_a2o[(size_t)MROWS*K2O];
__device__ __align__(256) __nv_bfloat16 g_b2o[(size_t)HH*K2O];
__device__ __align__(256) __half g_qh[(size_t)BB*NH*SS*HD];
__device__ __align__(256) __half g_ql[(size_t)BB*NH*SS*HD];
__device__ __align__(256) __half g_kh[(size_t)BB*NKV*SS*HD];
__device__ __align__(256) __half g_kl[(size_t)BB*NKV*SS*HD];
__device__ __align__(256) __half g_vh[(size_t)BB*NKV*SS*HD];

// ------------------------- PTX helpers --------------------------------------
__device__ __forceinline__ uint32_t smem_u32(const void* p) {
    uint32_t a;
    asm("{ .reg .u64 t; cvta.to.shared.u64 t, %1; cvt.u32.u64 %0, t; }" : "=r"(a) : "l"(p));
    return a;
}
__device__ __forceinline__ uint32_t h2u(__half2 v) {
    return *reinterpret_cast<uint32_t*>(&v);
}
__device__ __forceinline__ void cp_async16(uint32_t saddr, const void* gaddr) {
    asm volatile("cp.async.cg.shared.global [%0], [%1], 16;" :: "r"(saddr), "l"(gaddr) : "memory");
}
__device__ __forceinline__ void cp_commit() {
    asm volatile("cp.async.commit_group;" ::: "memory");
}
__device__ __forceinline__ void cp_wait2() {
    asm volatile("cp.async.wait_group 2;" ::: "memory");
}
__device__ __forceinline__ void cp_wait1() {
    asm volatile("cp.async.wait_group 1;" ::: "memory");
}
__device__ __forceinline__ void ldsm4(uint32_t* r, uint32_t addr) {
    asm volatile("ldmatrix.sync.aligned.m8n8.x4.shared.b16 {%0,%1,%2,%3}, [%4];"
                 : "=r"(r[0]), "=r"(r[1]), "=r"(r[2]), "=r"(r[3]) : "r"(addr));
}
__device__ __forceinline__ void ldsm4t(uint32_t* r, uint32_t addr) {
    asm volatile("ldmatrix.sync.aligned.m8n8.x4.trans.shared.b16 {%0,%1,%2,%3}, [%4];"
                 : "=r"(r[0]), "=r"(r[1]), "=r"(r[2]), "=r"(r[3]) : "r"(addr));
}
__device__ __forceinline__ void mma16816(float* c, const uint32_t* a, const uint32_t* b) {
    asm volatile(
        "mma.sync.aligned.m16n8k16.row.col.f32.bf16.bf16.f32 "
        "{%0,%1,%2,%3}, {%4,%5,%6,%7}, {%8,%9}, {%0,%1,%2,%3};"
        : "+f"(c[0]), "+f"(c[1]), "+f"(c[2]), "+f"(c[3])
        : "r"(a[0]), "r"(a[1]), "r"(a[2]), "r"(a[3]), "r"(b[0]), "r"(b[1]));
}
__device__ __forceinline__ void mma16816h(float* c, const uint32_t* a, uint32_t b0, uint32_t b1) {
    asm volatile(
        "mma.sync.aligned.m16n8k16.row.col.f32.f16.f16.f32 "
        "{%0,%1,%2,%3}, {%4,%5,%6,%7}, {%8,%9}, {%0,%1,%2,%3};"
        : "+f"(c[0]), "+f"(c[1]), "+f"(c[2]), "+f"(c[3])
        : "r"(a[0]), "r"(a[1]), "r"(a[2]), "r"(a[3]), "r"(b0), "r"(b1));
}
#define SWZ(off) ((off) ^ (((off) >> 3) & 0x70))

// byte offset of (row, d) inside a 64x256-half tile stored as 4 chunks of
// 64 rows x 128B, SW128-swizzled per chunk
__device__ __forceinline__ uint32_t tile_off(int row, int d) {
    uint32_t off = (uint32_t)(row * 128 + (d & 63) * 2);
    return (uint32_t)((d >> 6) * 8192) + SWZ(off);
}

// ------------------------- split-bf16 prep kernels --------------------------
__global__ __launch_bounds__(256) void split3_rows(
    const float* __restrict__ X, __nv_bfloat16* __restrict__ Y, int total, int K)
{
    int t = blockIdx.x * blockDim.x + threadIdx.x;
    if (t >= total) return;
    int m = t / K, k = t - m * K;
    float x = X[t];
    __nv_bfloat16 hi = __float2bfloat16(x);
    __nv_bfloat16 lo = __float2bfloat16(x - __bfloat162float(hi));
    size_t o = (size_t)m * (3 * (size_t)K) + 3 * (size_t)k;
    Y[o] = hi; Y[o + 1] = hi; Y[o + 2] = lo;
}
__global__ __launch_bounds__(256) void split3_transpose(
    const float* __restrict__ W, __nv_bfloat16* __restrict__ Y, int K, int N, int K2)
{
    __shared__ float t[32][33];
    int k0 = blockIdx.y * 32, n0 = blockIdx.x * 32;
    int tx = threadIdx.x & 31, ty = threadIdx.x >> 5;
#pragma unroll
    for (int i = 0; i < 4; i++)
        t[ty + i * 8][tx] = W[(size_t)(k0 + ty + i * 8) * N + n0 + tx];
    __syncthreads();
#pragma unroll
    for (int i = 0; i < 4; i++) {
        int n = n0 + ty + i * 8;
        int k = k0 + tx;
        float x = t[tx][ty + i * 8];
        __nv_bfloat16 hi = __float2bfloat16(x);
        __nv_bfloat16 lo = __float2bfloat16(x - __bfloat162float(hi));
        size_t o = (size_t)n * K2 + 3 * (size_t)k;
        Y[o] = hi; Y[o + 1] = lo; Y[o + 2] = hi;
    }
}

// ------------------------- HMMA GEMM (unchanged from R3) --------------------
__global__ __launch_bounds__(256) void gemm_tc(
    const __nv_bfloat16* __restrict__ A2, const __nv_bfloat16* __restrict__ B2,
    float* __restrict__ Cq, float* __restrict__ Ck, float* __restrict__ Cv,
    int K2, int mode, int ldN)
{
    extern __shared__ char dsm[];
    const int tid = threadIdx.x;
    const int wid = tid >> 5;
    const int lane = tid & 31;
    const int m0 = blockIdx.y * 128;
    const int n0 = blockIdx.x * 128;
    const int warpM = (wid & 3) * 32;
    const int warpN = (wid >> 2) * 64;

    uint32_t raw = smem_u32(dsm);
    uint32_t sbase = (raw + 1023u) & ~1023u;
    char* dtile = dsm + (sbase - raw);

    const int nk = K2 >> 6;
    const int colb = (tid & 7) * 16;
    const int r0 = tid >> 3;

    float c[2][8][4];
#pragma unroll
    for (int mi = 0; mi < 2; mi++)
#pragma unroll
        for (int nf = 0; nf < 8; nf++)
#pragma unroll
            for (int j = 0; j < 4; j++) c[mi][nf][j] = 0.f;

    const int lrow = lane & 15;
    const int lchunk = (lane >> 4) * 16;

#pragma unroll
    for (int s = 0; s < NST; s++) {
        uint32_t sA = sbase + s * STAGE_BYTES;
        uint32_t sB = sA + 16384;
        int k0 = s * 64;
#pragma unroll
        for (int i = 0; i < 4; i++) {
            int row = i * 32 + r0;
            uint32_t so = SWZ((uint32_t)(row * 128 + colb));
            cp_async16(sA + so, A2 + (size_t)(m0 + row) * K2 + k0 + (tid & 7) * 8);
            cp_async16(sB + so, B2 + (size_t)(n0 + row) * K2 + k0 + (tid & 7) * 8);
        }
        cp_commit();
    }

    for (int ck = 0; ck < nk; ck++) {
        const int s = ck - (ck / NST) * NST;
        cp_wait2();
        __syncthreads();

        uint32_t sA = sbase + s * STAGE_BYTES;
        uint32_t sB = sA + 16384;

#pragma unroll
        for (int ks = 0; ks < 4; ks++) {
            const int kb = ks * 32 + lchunk;
            uint32_t a[2][4], b[4][4];
#pragma unroll
            for (int mi = 0; mi < 2; mi++) {
                int row = warpM + mi * 16 + lrow;
                ldsm4(a[mi], sA + SWZ((uint32_t)(row * 128 + kb)));
            }
#pragma unroll
            for (int ni = 0; ni < 4; ni++) {
                int row = warpN + ni * 16 + lrow;
                ldsm4(b[ni], sB + SWZ((uint32_t)(row * 128 + kb)));
            }
#pragma unroll
            for (int mi = 0; mi < 2; mi++)
#pragma unroll
                for (int ni = 0; ni < 4; ni++) {
                    uint32_t blo[2] = { b[ni][0], b[ni][2] };
                    uint32_t bhi[2] = { b[ni][1], b[ni][3] };
                    mma16816(c[mi][2 * ni + 0], a[mi], blo);
                    mma16816(c[mi][2 * ni + 1], a[mi], bhi);
                }
        }
        __syncthreads();

        const int nck = ck + NST;
        if (nck < nk) {
            int k0 = nck * 64;
#pragma unroll
            for (int i = 0; i < 4; i++) {
                int row = i * 32 + r0;
                uint32_t so = SWZ((uint32_t)(row * 128 + colb));
                cp_async16(sA + so, A2 + (size_t)(m0 + row) * K2 + k0 + (tid & 7) * 8);
                cp_async16(sB + so, B2 + (size_t)(n0 + row) * K2 + k0 + (tid & 7) * 8);
            }
        }
        cp_commit();
    }

    __syncthreads();
    float* stile = (float*)dtile;
    {
        int rquad = lane >> 2;
        int cpair = (lane & 3) << 1;
#pragma unroll
        for (int mi = 0; mi < 2; mi++) {
            int rbase = warpM + mi * 16 + rquad;
#pragma unroll
            for (int nf = 0; nf < 8; nf++) {
                int col = warpN + nf * 8 + cpair;
                *(float2*)&stile[rbase * 132 + col]       = make_float2(c[mi][nf][0], c[mi][nf][1]);
                *(float2*)&stile[(rbase + 8) * 132 + col] = make_float2(c[mi][nf][2], c[mi][nf][3]);
            }
        }
    }
    __syncthreads();

    if (mode == 0) {
#pragma unroll
        for (int i = 0; i < 16; i++) {
            int idx = i * 256 + tid;
            int row = idx >> 5, c4 = idx & 31;
            float4 v = *(float4*)&stile[row * 132 + c4 * 4];
            int m = m0 + row;
            *(float4*)&Cq[(size_t)m * ldN + n0 + c4 * 4] = v;
        }
    } else {
        float* tens; int hh, hp;
        if (n0 < 2048)      { tens = Cq; hh = n0 >> 8;          hp = NH; }
        else if (n0 < 3072) { tens = Ck; hh = (n0 - 2048) >> 8; hp = NKV; }
        else                { tens = Cv; hh = (n0 - 3072) >> 8; hp = NKV; }
        int d0 = n0 & 255;
#pragma unroll
        for (int i = 0; i < 16; i++) {
            int idx = i * 256 + tid;
            int row = idx >> 5, c4 = idx & 31;
            float4 v = *(float4*)&stile[row * 132 + c4 * 4];
            int m = m0 + row;
            int b = m >> 11, sq = m & (SS - 1);
            *(float4*)&tens[(((size_t)(b * hp + hh)) * SS + sq) * HD + d0 + c4 * 4] = v;
        }
    }
}

// --------------- RoPE + fp16 hi/lo split conversion -------------------------
__global__ __launch_bounds__(256) void rope_split_h(
    const float* __restrict__ X, __half* __restrict__ Xh, __half* __restrict__ Xl,
    const int* __restrict__ pos_ids, int heads, float scale)
{
    int t = blockIdx.x * blockDim.x + threadIdx.x;
    int d = t & 127;
    int s = (t >> 7) & (SS - 1);
    int rest = t >> 18;
    int hh = rest % heads;
    int b  = rest / heads;
    if (b >= BB) return;
    float p = (float)pos_ids[b * SS + s];
    float inv = powf(10000.f, -(float)d * (1.f / 128.f));
    float ang = p * inv;
    float si, co;
    sincosf(ang, &si, &co);
    size_t base = (((size_t)b * heads + hh) * SS + s) * HD;
    float x1 = X[base + d], x2 = X[base + d + 128];
    float r1 = (x1 * co - x2 * si) * scale;
    float r2 = (x2 * co + x1 * si) * scale;
    __half h1 = __float2half(r1), h2 = __float2half(r2);
    Xh[base + d] = h1;       Xh[base + d + 128] = h2;
    Xl[base + d] = __float2half(r1 - __half2float(h1));
    Xl[base + d + 128] = __float2half(r2 - __half2float(h2));
}
__global__ __launch_bounds__(256) void conv_half(
    const float* __restrict__ X, __half* __restrict__ Y, int n)
{
    int t = blockIdx.x * blockDim.x + threadIdx.x;
    if (t < n) Y[t] = __float2half(X[t]);
}

// ------------------------- tensor-core flash attention ----------------------
// CTA: 128 thr (4 warps x m16), q-block 64, k-tiles of 64 keys.
// logits = (Qh+Ql)·Kh + Qh·Kl  with q pre-scaled by 1/(16*50); s = 50*tanh(acc)
__device__ __forceinline__ void load_tile_async(uint32_t sdst, const __half* g, int tid) {
#pragma unroll
    for (int i = 0; i < 16; i++) {
        int idx = i * 128 + tid;
        int row = idx >> 5;
        int d = (idx & 31) * 8;
        cp_async16(sdst + tile_off(row, d), g + row * HD + d);
    }
}

__global__ __launch_bounds__(128) void attn_tc(
    const __half* __restrict__ Qh, const __half* __restrict__ Ql,
    const __half* __restrict__ Kh, const __half* __restrict__ Kl,
    const __half* __restrict__ Vh, float* __restrict__ AO)
{
    extern __shared__ char dsm[];
    uint32_t raw = smem_u32(dsm);
    uint32_t sb = (raw + 1023u) & ~1023u;
    const uint32_t sQh = sb, sQl = sb + 32768, sKh = sb + 65536,
                   sKl = sb + 98304, sVh = sb + 131072;

    const int tid = threadIdx.x;
    const int wid = tid >> 5;
    const int lane = tid & 31;
    const int qblk = blockIdx.x;
    const int h = blockIdx.y;
    const int b = blockIdx.z;
    const int kv = h >> 1;
    const int warpM = wid * 16;

    const __half* qhp = Qh + (((size_t)(b * NH + h)) * SS + qblk * 64) * HD;
    const __half* qlp = Ql + (((size_t)(b * NH + h)) * SS + qblk * 64) * HD;
    const __half* khp = Kh + ((size_t)(b * NKV + kv)) * SS * HD;
    const __half* klp = Kl + ((size_t)(b * NKV + kv)) * SS * HD;
    const __half* vhp = Vh + ((size_t)(b * NKV + kv)) * SS * HD;

    int lo = qblk * 64 - (WIN - 1);
    if (lo < 0) lo = 0;
    lo &= ~63;
    const int hi = qblk * 64;

    // group 0: Q tiles + K(lo);  group 1: V(lo)
    load_tile_async(sQh, qhp, tid);
    load_tile_async(sQl, qlp, tid);
    load_tile_async(sKh, khp + (size_t)lo * HD, tid);
    load_tile_async(sKl, klp + (size_t)lo * HD, tid);
    cp_commit();
    load_tile_async(sVh, vhp + (size_t)lo * HD, tid);
    cp_commit();

    float oacc[32][4];
#pragma unroll
    for (int i = 0; i < 32; i++)
#pragma unroll
        for (int j = 0; j < 4; j++) oacc[i][j] = 0.f;
    float m0 = -1e30f, m1 = -1e30f, l0 = 0.f, l1 = 0.f;

    const int lrow = lane & 15;
    const int lhalf = (lane >> 4) * 16;   // byte offset of 16B half-row
    const int qi = qblk * 64 + warpM + (lane >> 2);

    for (int kt = lo; kt <= hi; kt += 64) {
        cp_wait1();            // K(kt) ready (and Q on first iter)
        __syncthreads();

        // ---- QK: sacc = Qh·Kh + Ql·Kh + Qh·Kl ----
        float sacc[8][4];
#pragma unroll
        for (int i = 0; i < 8; i++)
#pragma unroll
            for (int j = 0; j < 4; j++) sacc[i][j] = 0.f;

#pragma unroll
        for (int kc = 0; kc < 16; kc++) {
            const int c = kc >> 2;
            const int colb = (kc & 3) * 32 + lhalf;
            uint32_t aqh[4], aql[4];
            uint32_t aoff = (uint32_t)(c * 8192) + SWZ((uint32_t)((warpM + lrow) * 128 + colb));
            ldsm4(aqh, sQh + aoff);
            ldsm4(aql, sQl + aoff);
#pragma unroll
            for (int g = 0; g < 4; g++) {
                uint32_t boff = (uint32_t)(c * 8192) + SWZ((uint32_t)((g * 16 + lrow) * 128 + colb));
                uint32_t bh[4], bl[4];
                ldsm4(bh, sKh + boff);
                ldsm4(bl, sKl + boff);
                mma16816h(sacc[2 * g],     aqh, bh[0], bh[2]);
                mma16816h(sacc[2 * g + 1], aqh, bh[1], bh[3]);
                mma16816h(sacc[2 * g],     aql, bh[0], bh[2]);
                mma16816h(sacc[2 * g + 1], aql, bh[1], bh[3]);
                mma16816h(sacc[2 * g],     aqh, bl[0], bl[2]);
                mma16816h(sacc[2 * g + 1], aqh, bl[1], bl[3]);
            }
        }
        __syncthreads();       // K consumed
        if (kt + 64 <= hi) {
            load_tile_async(sKh, khp + (size_t)(kt + 64) * HD, tid);
            load_tile_async(sKl, klp + (size_t)(kt + 64) * HD, tid);
        }
        cp_commit();           // group: K(next)

        // ---- softcap + mask ----
        float tm0 = -1e30f, tm1 = -1e30f;
#pragma unroll
        for (int nt = 0; nt < 8; nt++) {
#pragma unroll
            for (int j = 0; j < 4; j++) {
                int kj = kt + nt * 8 + (lane & 3) * 2 + (j & 1);
                int row = qi + ((j >> 1) * 8);
                float x = sacc[nt][j];
                float e = __expf(2.f * x);
                float s = 50.f * __fdividef(e - 1.f, e + 1.f);
                bool ok = (kj <= row) && (row - kj < WIN);
                s = ok ? s : -1e30f;
                sacc[nt][j] = s;
                if (j < 2) tm0 = fmaxf(tm0, s); else tm1 = fmaxf(tm1, s);
            }
        }
        tm0 = fmaxf(tm0, __shfl_xor_sync(0xffffffffu, tm0, 1));
        tm0 = fmaxf(tm0, __shfl_xor_sync(0xffffffffu, tm0, 2));
        tm1 = fmaxf(tm1, __shfl_xor_sync(0xffffffffu, tm1, 1));
        tm1 = fmaxf(tm1, __shfl_xor_sync(0xffffffffu, tm1, 2));

        float mn0 = fmaxf(m0, tm0), mn1 = fmaxf(m1, tm1);
        float al0 = __expf(m0 - mn0), al1 = __expf(m1 - mn1);
        m0 = mn0; m1 = mn1;

        float rs0 = 0.f, rs1 = 0.f;
#pragma unroll
        for (int nt = 0; nt < 8; nt++) {
            float p0 = __expf(sacc[nt][0] - mn0);
            float p1 = __expf(sacc[nt][1] - mn0);
            float p2 = __expf(sacc[nt][2] - mn1);
            float p3 = __expf(sacc[nt][3] - mn1);
            sacc[nt][0] = p0; sacc[nt][1] = p1; sacc[nt][2] = p2; sacc[nt][3] = p3;
            rs0 += p0 + p1; rs1 += p2 + p3;
        }
        rs0 += __shfl_xor_sync(0xffffffffu, rs0, 1);
        rs0 += __shfl_xor_sync(0xffffffffu, rs0, 2);
        rs1 += __shfl_xor_sync(0xffffffffu, rs1, 1);
        rs1 += __shfl_xor_sync(0xffffffffu, rs1, 2);
        l0 = l0 * al0 + rs0;
        l1 = l1 * al1 + rs1;

        // P -> fp16 A-frags
        uint32_t aP[4][4];
#pragma unroll
        for (int kc2 = 0; kc2 < 4; kc2++) {
            aP[kc2][0] = h2u(__floats2half2_rn(sacc[2 * kc2][0],     sacc[2 * kc2][1]));
            aP[kc2][1] = h2u(__floats2half2_rn(sacc[2 * kc2][2],     sacc[2 * kc2][3]));
            aP[kc2][2] = h2u(__floats2half2_rn(sacc[2 * kc2 + 1][0], sacc[2 * kc2 + 1][1]));
            aP[kc2][3] = h2u(__floats2half2_rn(sacc[2 * kc2 + 1][2], sacc[2 * kc2 + 1][3]));
        }

        // rescale O
#pragma unroll
        for (int dt = 0; dt < 32; dt++) {
            oacc[dt][0] *= al0; oacc[dt][1] *= al0;
            oacc[dt][2] *= al1; oacc[dt][3] *= al1;
        }

        cp_wait1();            // V(kt) ready
        __syncthreads();

        // ---- PV: O += P · V ----
#pragma unroll
        for (int kc2 = 0; kc2 < 4; kc2++) {
#pragma unroll
            for (int dg = 0; dg < 16; dg++) {
                int key = kc2 * 16 + lrow;
                int d = dg * 16 + (lane >> 4) * 8;
                uint32_t r[4];
                ldsm4t(r, sVh + tile_off(key, d));
                mma16816h(oacc[dg * 2],     aP[kc2], r[0], r[1]);
                mma16816h(oacc[dg * 2 + 1], aP[kc2], r[2], r[3]);
            }
        }
        __syncthreads();       // V consumed
        if (kt + 64 <= hi)
            load_tile_async(sVh, vhp + (size_t)(kt + 64) * HD, tid);
        cp_commit();           // group: V(next)
    }

    // ---- epilogue ----
    float il0 = __fdividef(1.f, l0);
    float il1 = __fdividef(1.f, l1);
    float* o0 = AO + ((size_t)(b * SS + qi)) * (NH * HD) + h * HD;
    float* o1 = AO + ((size_t)(b * SS + qi + 8)) * (NH * HD) + h * HD;
    int cbase = (lane & 3) * 2;
#pragma unroll
    for (int dt = 0; dt < 32; dt++) {
        int col = dt * 8 + cbase;
        *(float2*)&o0[col] = make_float2(oacc[dt][0] * il0, oacc[dt][1] * il0);
        *(float2*)&o1[col] = make_float2(oacc[dt][2] * il1, oacc[dt][3] * il1);
    }
}

// ---------------------------------------------------------------------------
extern "C" void kernel_launch(void* const* d_in, const int* in_sizes, int n_in,
                              void* d_out, int out_size)
{
    const float* hid = (const float*)d_in[0];
    const int*   pos = (const int*)d_in[2];
    const float* Wq  = (const float*)d_in[3];
    const float* Wk  = (const float*)d_in[4];
    const float* Wv  = (const float*)d_in[5];
    const float* Wo  = (const float*)d_in[6];
    float* out = (float*)d_out;

    float *qp, *kp, *vp, *aop;
    __nv_bfloat16 *a2, *b2, *a2o, *b2o;
    __half *qh_, *ql_, *kh_, *kl_, *vh_;
    cudaGetSymbolAddress((void**)&qp,  g_q);
    cudaGetSymbolAddress((void**)&kp,  g_k);
    cudaGetSymbolAddress((void**)&vp,  g_v);
    cudaGetSymbolAddress((void**)&aop, g_ao);
    cudaGetSymbolAddress((void**)&a2,  g_a2);
    cudaGetSymbolAddress((void**)&b2,  g_b2);
    cudaGetSymbolAddress((void**)&a2o, g_a2o);
    cudaGetSymbolAddress((void**)&b2o, g_b2o);
    cudaGetSymbolAddress((void**)&qh_, g_qh);
    cudaGetSymbolAddress((void**)&ql_, g_ql);
    cudaGetSymbolAddress((void**)&kh_, g_kh);
    cudaGetSymbolAddress((void**)&kl_, g_kl);
    cudaGetSymbolAddress((void**)&vh_, g_vh);

    cudaFuncSetAttribute(gemm_tc, cudaFuncAttributeMaxDynamicSharedMemorySize, GEMM_SMEM);
    cudaFuncSetAttribute(attn_tc, cudaFuncAttributeMaxDynamicSharedMemorySize, ATT_SMEM);

    // ---- QKV projections (bf16x3 HMMA) ----
    split3_rows<<<(MROWS*HH + 255)/256, 256>>>(hid, a2, MROWS*HH, HH);
    split3_transpose<<<dim3(2048/32, HH/32), 256>>>(Wq, b2, HH, 2048, K2QKV);
    split3_transpose<<<dim3(1024/32, HH/32), 256>>>(Wk, b2 + (size_t)2048*K2QKV, HH, 1024, K2QKV);
    split3_transpose<<<dim3(1024/32, HH/32), 256>>>(Wv, b2 + (size_t)3072*K2QKV, HH, 1024, K2QKV);
    gemm_tc<<<dim3(NQKV/128, MROWS/128), 256, GEMM_SMEM>>>(a2, b2, qp, kp, vp, K2QKV, 1, 0);

    // ---- RoPE + fp16 split conversion ----
    rope_split_h<<<(BB*NH*SS*128)/256, 256>>>(qp, qh_, ql_, pos, NH, 1.f/(16.f*50.f));
    rope_split_h<<<(BB*NKV*SS*128)/256, 256>>>(kp, kh_, kl_, pos, NKV, 1.f);
    conv_half<<<(BB*NKV*SS*HD)/256, 256>>>(vp, vh_, BB*NKV*SS*HD);

    // ---- flash attention (fp16 HMMA) ----
    attn_tc<<<dim3(SS/64, NH, BB), 128, ATT_SMEM>>>(qh_, ql_, kh_, kl_, vh_, aop);

    // ---- out projection ----
    split3_rows<<<(MROWS*2048 + 255)/256, 256>>>(aop, a2o, MROWS*2048, 2048);
    split3_transpose<<<dim3(HH/32, 2048/32), 256>>>(Wo, b2o, 2048, HH, K2O);
    gemm_tc<<<dim3(HH/128, MROWS/128), 256, GEMM_SMEM>>>(a2o, b2o, out, nullptr, nullptr, K2O, 0, HH);
}

// round 6
// speedup vs baseline: 4.9848x; 1.4322x over previous
#include <cuda_runtime.h>
#include <cuda_fp16.h>
#include <cstdint>
#include <math.h>

#define BB   2
#define SS   2048
#define HH   2304
#define NH   8
#define HD   256
#define NKV  4
#define WIN  512
#define MROWS (BB*SS)            // 4096
#define K2QKV (2*HH)             // 4608
#define K2O   (2*2048)           // 4096
#define NQKV  (NH*HD + 2*NKV*HD) // 4096
#define NST   3
#define STAGE_BYTES 32768
#define GEMM_SMEM (NST*STAGE_BYTES + 1024)
#define ATT_SMEM (4*32768 + 1024)   // Qh Ql Kh Vh tiles (32KB each) + align

// ------------------------- device scratch (no allocs allowed) ---------------
__device__ float g_q[(size_t)BB*NH*SS*HD];
__device__ float g_k[(size_t)BB*NKV*SS*HD];
__device__ float g_v[(size_t)BB*NKV*SS*HD];
__device__ __align__(256) __half g_a2 [(size_t)MROWS*K2QKV];
__device__ __align__(256) __half g_b2 [(size_t)NQKV*K2QKV];
__device__ __align__(256) __half g_a2o[(size_t)MROWS*K2O];
__device__ __align__(256) __half g_b2o[(size_t)HH*K2O];
__device__ __align__(256) __half g_qh[(size_t)BB*NH*SS*HD];
__device__ __align__(256) __half g_ql[(size_t)BB*NH*SS*HD];
__device__ __align__(256) __half g_kh[(size_t)BB*NKV*SS*HD];
__device__ __align__(256) __half g_vh[(size_t)BB*NKV*SS*HD];

// ------------------------- PTX helpers --------------------------------------
__device__ __forceinline__ uint32_t smem_u32(const void* p) {
    uint32_t a;
    asm("{ .reg .u64 t; cvta.to.shared.u64 t, %1; cvt.u32.u64 %0, t; }" : "=r"(a) : "l"(p));
    return a;
}
__device__ __forceinline__ uint32_t h2u(__half2 v) {
    return *reinterpret_cast<uint32_t*>(&v);
}
__device__ __forceinline__ void cp_async16(uint32_t saddr, const void* gaddr) {
    asm volatile("cp.async.cg.shared.global [%0], [%1], 16;" :: "r"(saddr), "l"(gaddr) : "memory");
}
__device__ __forceinline__ void cp_commit() {
    asm volatile("cp.async.commit_group;" ::: "memory");
}
__device__ __forceinline__ void cp_wait2() {
    asm volatile("cp.async.wait_group 2;" ::: "memory");
}
__device__ __forceinline__ void cp_wait1() {
    asm volatile("cp.async.wait_group 1;" ::: "memory");
}
__device__ __forceinline__ void ldsm4(uint32_t* r, uint32_t addr) {
    asm volatile("ldmatrix.sync.aligned.m8n8.x4.shared.b16 {%0,%1,%2,%3}, [%4];"
                 : "=r"(r[0]), "=r"(r[1]), "=r"(r[2]), "=r"(r[3]) : "r"(addr));
}
__device__ __forceinline__ void ldsm4t(uint32_t* r, uint32_t addr) {
    asm volatile("ldmatrix.sync.aligned.m8n8.x4.trans.shared.b16 {%0,%1,%2,%3}, [%4];"
                 : "=r"(r[0]), "=r"(r[1]), "=r"(r[2]), "=r"(r[3]) : "r"(addr));
}
__device__ __forceinline__ void mma16816h(float* c, const uint32_t* a, uint32_t b0, uint32_t b1) {
    asm volatile(
        "mma.sync.aligned.m16n8k16.row.col.f32.f16.f16.f32 "
        "{%0,%1,%2,%3}, {%4,%5,%6,%7}, {%8,%9}, {%0,%1,%2,%3};"
        : "+f"(c[0]), "+f"(c[1]), "+f"(c[2]), "+f"(c[3])
        : "r"(a[0]), "r"(a[1]), "r"(a[2]), "r"(a[3]), "r"(b0), "r"(b1));
}
#define SWZ(off) ((off) ^ (((off) >> 3) & 0x70))

// byte offset of (row, d) inside a 64x256-half tile: 4 chunks of 64 rows x 128B
__device__ __forceinline__ uint32_t tile_off(int row, int d) {
    uint32_t off = (uint32_t)(row * 128 + (d & 63) * 2);
    return (uint32_t)((d >> 6) * 8192) + SWZ(off);
}

// ------------------------- split-fp16 prep kernels --------------------------
// A side: per original k, emit {hi, lo}
__global__ __launch_bounds__(256) void split2_rows(
    const float* __restrict__ X, __half* __restrict__ Y, int total, int K)
{
    int t = blockIdx.x * blockDim.x + threadIdx.x;
    if (t >= total) return;
    int m = t / K, k = t - m * K;
    float x = X[t];
    __half hi = __float2half(x);
    __half lo = __float2half(x - __half2float(hi));
    size_t o = (size_t)m * (2 * (size_t)K) + 2 * (size_t)k;
    Y[o] = hi; Y[o + 1] = lo;
}
// B side: W[K,N] -> Y[n, 2k+{0,1}] = {hh, hh}  (transpose + fp16 quantize)
__global__ __launch_bounds__(256) void split2_transpose(
    const float* __restrict__ W, __half* __restrict__ Y, int K, int N, int K2)
{
    __shared__ float t[32][33];
    int k0 = blockIdx.y * 32, n0 = blockIdx.x * 32;
    int tx = threadIdx.x & 31, ty = threadIdx.x >> 5;
#pragma unroll
    for (int i = 0; i < 4; i++)
        t[ty + i * 8][tx] = W[(size_t)(k0 + ty + i * 8) * N + n0 + tx];
    __syncthreads();
#pragma unroll
    for (int i = 0; i < 4; i++) {
        int n = n0 + ty + i * 8;
        int k = k0 + tx;
        __half hh = __float2half(t[tx][ty + i * 8]);
        size_t o = (size_t)n * K2 + 2 * (size_t)k;
        Y[o] = hh; Y[o + 1] = hh;
    }
}

// ------------------------- HMMA GEMM (fp16 operands) ------------------------
// C[M,N] = A2[M,K2] @ B2[N,K2]^T,  fp32 accum.
// Block 128x128, 8 warps (4m x 2n), warp tile 32x64, K-chunk 64.
__global__ __launch_bounds__(256) void gemm_tc(
    const __half* __restrict__ A2, const __half* __restrict__ B2,
    float* __restrict__ Cq, float* __restrict__ Ck, float* __restrict__ Cv,
    int K2, int mode, int ldN)
{
    extern __shared__ char dsm[];
    const int tid = threadIdx.x;
    const int wid = tid >> 5;
    const int lane = tid & 31;
    const int m0 = blockIdx.y * 128;
    const int n0 = blockIdx.x * 128;
    const int warpM = (wid & 3) * 32;
    const int warpN = (wid >> 2) * 64;

    uint32_t raw = smem_u32(dsm);
    uint32_t sbase = (raw + 1023u) & ~1023u;
    char* dtile = dsm + (sbase - raw);

    const int nk = K2 >> 6;
    const int colb = (tid & 7) * 16;
    const int r0 = tid >> 3;

    float c[2][8][4];
#pragma unroll
    for (int mi = 0; mi < 2; mi++)
#pragma unroll
        for (int nf = 0; nf < 8; nf++)
#pragma unroll
            for (int j = 0; j < 4; j++) c[mi][nf][j] = 0.f;

    const int lrow = lane & 15;
    const int lchunk = (lane >> 4) * 16;

#pragma unroll
    for (int s = 0; s < NST; s++) {
        uint32_t sA = sbase + s * STAGE_BYTES;
        uint32_t sB = sA + 16384;
        int k0 = s * 64;
#pragma unroll
        for (int i = 0; i < 4; i++) {
            int row = i * 32 + r0;
            uint32_t so = SWZ((uint32_t)(row * 128 + colb));
            cp_async16(sA + so, A2 + (size_t)(m0 + row) * K2 + k0 + (tid & 7) * 8);
            cp_async16(sB + so, B2 + (size_t)(n0 + row) * K2 + k0 + (tid & 7) * 8);
        }
        cp_commit();
    }

    for (int ck = 0; ck < nk; ck++) {
        const int s = ck - (ck / NST) * NST;
        cp_wait2();
        __syncthreads();

        uint32_t sA = sbase + s * STAGE_BYTES;
        uint32_t sB = sA + 16384;

#pragma unroll
        for (int ks = 0; ks < 4; ks++) {
            const int kb = ks * 32 + lchunk;
            uint32_t a[2][4], b[4][4];
#pragma unroll
            for (int mi = 0; mi < 2; mi++) {
                int row = warpM + mi * 16 + lrow;
                ldsm4(a[mi], sA + SWZ((uint32_t)(row * 128 + kb)));
            }
#pragma unroll
            for (int ni = 0; ni < 4; ni++) {
                int row = warpN + ni * 16 + lrow;
                ldsm4(b[ni], sB + SWZ((uint32_t)(row * 128 + kb)));
            }
#pragma unroll
            for (int mi = 0; mi < 2; mi++)
#pragma unroll
                for (int ni = 0; ni < 4; ni++) {
                    mma16816h(c[mi][2 * ni + 0], a[mi], b[ni][0], b[ni][2]);
                    mma16816h(c[mi][2 * ni + 1], a[mi], b[ni][1], b[ni][3]);
                }
        }
        __syncthreads();

        const int nck = ck + NST;
        if (nck < nk) {
            int k0 = nck * 64;
#pragma unroll
            for (int i = 0; i < 4; i++) {
                int row = i * 32 + r0;
                uint32_t so = SWZ((uint32_t)(row * 128 + colb));
                cp_async16(sA + so, A2 + (size_t)(m0 + row) * K2 + k0 + (tid & 7) * 8);
                cp_async16(sB + so, B2 + (size_t)(n0 + row) * K2 + k0 + (tid & 7) * 8);
            }
        }
        cp_commit();
    }

    __syncthreads();
    float* stile = (float*)dtile;
    {
        int rquad = lane >> 2;
        int cpair = (lane & 3) << 1;
#pragma unroll
        for (int mi = 0; mi < 2; mi++) {
            int rbase = warpM + mi * 16 + rquad;
#pragma unroll
            for (int nf = 0; nf < 8; nf++) {
                int col = warpN + nf * 8 + cpair;
                *(float2*)&stile[rbase * 132 + col]       = make_float2(c[mi][nf][0], c[mi][nf][1]);
                *(float2*)&stile[(rbase + 8) * 132 + col] = make_float2(c[mi][nf][2], c[mi][nf][3]);
            }
        }
    }
    __syncthreads();

    if (mode == 0) {
#pragma unroll
        for (int i = 0; i < 16; i++) {
            int idx = i * 256 + tid;
            int row = idx >> 5, c4 = idx & 31;
            float4 v = *(float4*)&stile[row * 132 + c4 * 4];
            int m = m0 + row;
            *(float4*)&Cq[(size_t)m * ldN + n0 + c4 * 4] = v;
        }
    } else {
        float* tens; int hh, hp;
        if (n0 < 2048)      { tens = Cq; hh = n0 >> 8;          hp = NH; }
        else if (n0 < 3072) { tens = Ck; hh = (n0 - 2048) >> 8; hp = NKV; }
        else                { tens = Cv; hh = (n0 - 3072) >> 8; hp = NKV; }
        int d0 = n0 & 255;
#pragma unroll
        for (int i = 0; i < 16; i++) {
            int idx = i * 256 + tid;
            int row = idx >> 5, c4 = idx & 31;
            float4 v = *(float4*)&stile[row * 132 + c4 * 4];
            int m = m0 + row;
            int b = m >> 11, sq = m & (SS - 1);
            *(float4*)&tens[(((size_t)(b * hp + hh)) * SS + sq) * HD + d0 + c4 * 4] = v;
        }
    }
}

// --------------- RoPE + fp16 conversions ------------------------------------
__global__ __launch_bounds__(256) void rope_split_h(
    const float* __restrict__ X, __half* __restrict__ Xh, __half* __restrict__ Xl,
    const int* __restrict__ pos_ids, int heads, float scale)
{
    int t = blockIdx.x * blockDim.x + threadIdx.x;
    int d = t & 127;
    int s = (t >> 7) & (SS - 1);
    int rest = t >> 18;
    int hh = rest % heads;
    int b  = rest / heads;
    if (b >= BB) return;
    float p = (float)pos_ids[b * SS + s];
    float inv = powf(10000.f, -(float)d * (1.f / 128.f));
    float ang = p * inv;
    float si, co;
    sincosf(ang, &si, &co);
    size_t base = (((size_t)b * heads + hh) * SS + s) * HD;
    float x1 = X[base + d], x2 = X[base + d + 128];
    float r1 = (x1 * co - x2 * si) * scale;
    float r2 = (x2 * co + x1 * si) * scale;
    __half h1 = __float2half(r1), h2 = __float2half(r2);
    Xh[base + d] = h1;       Xh[base + d + 128] = h2;
    Xl[base + d] = __float2half(r1 - __half2float(h1));
    Xl[base + d + 128] = __float2half(r2 - __half2float(h2));
}
__global__ __launch_bounds__(256) void rope_h(
    const float* __restrict__ X, __half* __restrict__ Xh,
    const int* __restrict__ pos_ids, int heads)
{
    int t = blockIdx.x * blockDim.x + threadIdx.x;
    int d = t & 127;
    int s = (t >> 7) & (SS - 1);
    int rest = t >> 18;
    int hh = rest % heads;
    int b  = rest / heads;
    if (b >= BB) return;
    float p = (float)pos_ids[b * SS + s];
    float inv = powf(10000.f, -(float)d * (1.f / 128.f));
    float ang = p * inv;
    float si, co;
    sincosf(ang, &si, &co);
    size_t base = (((size_t)b * heads + hh) * SS + s) * HD;
    float x1 = X[base + d], x2 = X[base + d + 128];
    Xh[base + d]       = __float2half(x1 * co - x2 * si);
    Xh[base + d + 128] = __float2half(x2 * co + x1 * si);
}
__global__ __launch_bounds__(256) void conv_half(
    const float* __restrict__ X, __half* __restrict__ Y, int n)
{
    int t = blockIdx.x * blockDim.x + threadIdx.x;
    if (t < n) Y[t] = __float2half(X[t]);
}

// ------------------------- tensor-core flash attention ----------------------
// CTA: 128 thr (4 warps x m16), q-block 64, k-tiles of 64 keys.
// logits = (Qh+Ql)·Kh with q pre-scaled by 1/(16*50); s = 50*tanh(acc)
// Epilogue writes split-2 fp16 directly into out-proj A buffer.
__device__ __forceinline__ void load_tile_async(uint32_t sdst, const __half* g, int tid) {
#pragma unroll
    for (int i = 0; i < 16; i++) {
        int idx = i * 128 + tid;
        int row = idx >> 5;
        int d = (idx & 31) * 8;
        cp_async16(sdst + tile_off(row, d), g + row * HD + d);
    }
}

__global__ __launch_bounds__(128) void attn_tc(
    const __half* __restrict__ Qh, const __half* __restrict__ Ql,
    const __half* __restrict__ Kh, const __half* __restrict__ Vh,
    __half* __restrict__ A2O)
{
    extern __shared__ char dsm[];
    uint32_t raw = smem_u32(dsm);
    uint32_t sb = (raw + 1023u) & ~1023u;
    const uint32_t sQh = sb, sQl = sb + 32768, sKh = sb + 65536, sVh = sb + 98304;

    const int tid = threadIdx.x;
    const int wid = tid >> 5;
    const int lane = tid & 31;
    const int qblk = blockIdx.x;
    const int h = blockIdx.y;
    const int b = blockIdx.z;
    const int kv = h >> 1;
    const int warpM = wid * 16;

    const __half* qhp = Qh + (((size_t)(b * NH + h)) * SS + qblk * 64) * HD;
    const __half* qlp = Ql + (((size_t)(b * NH + h)) * SS + qblk * 64) * HD;
    const __half* khp = Kh + ((size_t)(b * NKV + kv)) * SS * HD;
    const __half* vhp = Vh + ((size_t)(b * NKV + kv)) * SS * HD;

    int lo = qblk * 64 - (WIN - 1);
    if (lo < 0) lo = 0;
    lo &= ~63;
    const int hi = qblk * 64;

    // group 0: Q tiles + K(lo);  group 1: V(lo)
    load_tile_async(sQh, qhp, tid);
    load_tile_async(sQl, qlp, tid);
    load_tile_async(sKh, khp + (size_t)lo * HD, tid);
    cp_commit();
    load_tile_async(sVh, vhp + (size_t)lo * HD, tid);
    cp_commit();

    float oacc[32][4];
#pragma unroll
    for (int i = 0; i < 32; i++)
#pragma unroll
        for (int j = 0; j < 4; j++) oacc[i][j] = 0.f;
    float m0 = -1e30f, m1 = -1e30f, l0 = 0.f, l1 = 0.f;

    const int lrow = lane & 15;
    const int lhalf = (lane >> 4) * 16;
    const int qi = qblk * 64 + warpM + (lane >> 2);

    for (int kt = lo; kt <= hi; kt += 64) {
        cp_wait1();
        __syncthreads();

        // ---- QK: sacc = (Qh + Ql)·Kh ----
        float sacc[8][4];
#pragma unroll
        for (int i = 0; i < 8; i++)
#pragma unroll
            for (int j = 0; j < 4; j++) sacc[i][j] = 0.f;

#pragma unroll
        for (int kc = 0; kc < 16; kc++) {
            const int c = kc >> 2;
            const int colb = (kc & 3) * 32 + lhalf;
            uint32_t aqh[4], aql[4];
            uint32_t aoff = (uint32_t)(c * 8192) + SWZ((uint32_t)((warpM + lrow) * 128 + colb));
            ldsm4(aqh, sQh + aoff);
            ldsm4(aql, sQl + aoff);
#pragma unroll
            for (int g = 0; g < 4; g++) {
                uint32_t boff = (uint32_t)(c * 8192) + SWZ((uint32_t)((g * 16 + lrow) * 128 + colb));
                uint32_t bh[4];
                ldsm4(bh, sKh + boff);
                mma16816h(sacc[2 * g],     aqh, bh[0], bh[2]);
                mma16816h(sacc[2 * g + 1], aqh, bh[1], bh[3]);
                mma16816h(sacc[2 * g],     aql, bh[0], bh[2]);
                mma16816h(sacc[2 * g + 1], aql, bh[1], bh[3]);
            }
        }
        __syncthreads();
        if (kt + 64 <= hi)
            load_tile_async(sKh, khp + (size_t)(kt + 64) * HD, tid);
        cp_commit();

        // ---- softcap + mask ----
        float tm0 = -1e30f, tm1 = -1e30f;
#pragma unroll
        for (int nt = 0; nt < 8; nt++) {
#pragma unroll
            for (int j = 0; j < 4; j++) {
                int kj = kt + nt * 8 + (lane & 3) * 2 + (j & 1);
                int row = qi + ((j >> 1) * 8);
                float x = sacc[nt][j];
                float e = __expf(2.f * x);
                float s = 50.f * __fdividef(e - 1.f, e + 1.f);
                bool ok = (kj <= row) && (row - kj < WIN);
                s = ok ? s : -1e30f;
                sacc[nt][j] = s;
                if (j < 2) tm0 = fmaxf(tm0, s); else tm1 = fmaxf(tm1, s);
            }
        }
        tm0 = fmaxf(tm0, __shfl_xor_sync(0xffffffffu, tm0, 1));
        tm0 = fmaxf(tm0, __shfl_xor_sync(0xffffffffu, tm0, 2));
        tm1 = fmaxf(tm1, __shfl_xor_sync(0xffffffffu, tm1, 1));
        tm1 = fmaxf(tm1, __shfl_xor_sync(0xffffffffu, tm1, 2));

        float mn0 = fmaxf(m0, tm0), mn1 = fmaxf(m1, tm1);
        float al0 = __expf(m0 - mn0), al1 = __expf(m1 - mn1);
        m0 = mn0; m1 = mn1;

        float rs0 = 0.f, rs1 = 0.f;
#pragma unroll
        for (int nt = 0; nt < 8; nt++) {
            float p0 = __expf(sacc[nt][0] - mn0);
            float p1 = __expf(sacc[nt][1] - mn0);
            float p2 = __expf(sacc[nt][2] - mn1);
            float p3 = __expf(sacc[nt][3] - mn1);
            sacc[nt][0] = p0; sacc[nt][1] = p1; sacc[nt][2] = p2; sacc[nt][3] = p3;
            rs0 += p0 + p1; rs1 += p2 + p3;
        }
        rs0 += __shfl_xor_sync(0xffffffffu, rs0, 1);
        rs0 += __shfl_xor_sync(0xffffffffu, rs0, 2);
        rs1 += __shfl_xor_sync(0xffffffffu, rs1, 1);
        rs1 += __shfl_xor_sync(0xffffffffu, rs1, 2);
        l0 = l0 * al0 + rs0;
        l1 = l1 * al1 + rs1;

        // P -> fp16 A-frags
        uint32_t aP[4][4];
#pragma unroll
        for (int kc2 = 0; kc2 < 4; kc2++) {
            aP[kc2][0] = h2u(__floats2half2_rn(sacc[2 * kc2][0],     sacc[2 * kc2][1]));
            aP[kc2][1] = h2u(__floats2half2_rn(sacc[2 * kc2][2],     sacc[2 * kc2][3]));
            aP[kc2][2] = h2u(__floats2half2_rn(sacc[2 * kc2 + 1][0], sacc[2 * kc2 + 1][1]));
            aP[kc2][3] = h2u(__floats2half2_rn(sacc[2 * kc2 + 1][2], sacc[2 * kc2 + 1][3]));
        }

#pragma unroll
        for (int dt = 0; dt < 32; dt++) {
            oacc[dt][0] *= al0; oacc[dt][1] *= al0;
            oacc[dt][2] *= al1; oacc[dt][3] *= al1;
        }

        cp_wait1();
        __syncthreads();

        // ---- PV ----
#pragma unroll
        for (int kc2 = 0; kc2 < 4; kc2++) {
#pragma unroll
            for (int dg = 0; dg < 16; dg++) {
                int key = kc2 * 16 + lrow;
                int d = dg * 16 + (lane >> 4) * 8;
                uint32_t r[4];
                ldsm4t(r, sVh + tile_off(key, d));
                mma16816h(oacc[dg * 2],     aP[kc2], r[0], r[1]);
                mma16816h(oacc[dg * 2 + 1], aP[kc2], r[2], r[3]);
            }
        }
        __syncthreads();
        if (kt + 64 <= hi)
            load_tile_async(sVh, vhp + (size_t)(kt + 64) * HD, tid);
        cp_commit();
    }

    // ---- epilogue: write split-2 fp16 directly into out-proj A buffer ----
    float il0 = __fdividef(1.f, l0);
    float il1 = __fdividef(1.f, l1);
    __half* a0 = A2O + ((size_t)(b * SS + qi)) * K2O + 2 * (h * HD);
    __half* a1 = A2O + ((size_t)(b * SS + qi + 8)) * K2O + 2 * (h * HD);
    int cbase = (lane & 3) * 2;
#pragma unroll
    for (int dt = 0; dt < 32; dt++) {
        int col = dt * 8 + cbase;
        float v0 = oacc[dt][0] * il0, v1 = oacc[dt][1] * il0;
        float v2 = oacc[dt][2] * il1, v3 = oacc[dt][3] * il1;
        __half h0 = __float2half(v0), h1v = __float2half(v1);
        __half h2v = __float2half(v2), h3 = __float2half(v3);
        __half2 p0 = __halves2half2(h0, __float2half(v0 - __half2float(h0)));
        __half2 p1 = __halves2half2(h1v, __float2half(v1 - __half2float(h1v)));
        __half2 p2 = __halves2half2(h2v, __float2half(v2 - __half2float(h2v)));
        __half2 p3 = __halves2half2(h3, __float2half(v3 - __half2float(h3)));
        *(__half2*)&a0[2 * col]     = p0;
        *(__half2*)&a0[2 * col + 2] = p1;
        *(__half2*)&a1[2 * col]     = p2;
        *(__half2*)&a1[2 * col + 2] = p3;
    }
}

// ---------------------------------------------------------------------------
extern "C" void kernel_launch(void* const* d_in, const int* in_sizes, int n_in,
                              void* d_out, int out_size)
{
    const float* hid = (const float*)d_in[0];
    const int*   pos = (const int*)d_in[2];
    const float* Wq  = (const float*)d_in[3];
    const float* Wk  = (const float*)d_in[4];
    const float* Wv  = (const float*)d_in[5];
    const float* Wo  = (const float*)d_in[6];
    float* out = (float*)d_out;

    float *qp, *kp, *vp;
    __half *a2, *b2, *a2o, *b2o, *qh_, *ql_, *kh_, *vh_;
    cudaGetSymbolAddress((void**)&qp,  g_q);
    cudaGetSymbolAddress((void**)&kp,  g_k);
    cudaGetSymbolAddress((void**)&vp,  g_v);
    cudaGetSymbolAddress((void**)&a2,  g_a2);
    cudaGetSymbolAddress((void**)&b2,  g_b2);
    cudaGetSymbolAddress((void**)&a2o, g_a2o);
    cudaGetSymbolAddress((void**)&b2o, g_b2o);
    cudaGetSymbolAddress((void**)&qh_, g_qh);
    cudaGetSymbolAddress((void**)&ql_, g_ql);
    cudaGetSymbolAddress((void**)&kh_, g_kh);
    cudaGetSymbolAddress((void**)&vh_, g_vh);

    cudaFuncSetAttribute(gemm_tc, cudaFuncAttributeMaxDynamicSharedMemorySize, GEMM_SMEM);
    cudaFuncSetAttribute(attn_tc, cudaFuncAttributeMaxDynamicSharedMemorySize, ATT_SMEM);

    // ---- QKV projections (fp16 split-2 HMMA) ----
    split2_rows<<<(MROWS*HH + 255)/256, 256>>>(hid, a2, MROWS*HH, HH);
    split2_transpose<<<dim3(2048/32, HH/32), 256>>>(Wq, b2, HH, 2048, K2QKV);
    split2_transpose<<<dim3(1024/32, HH/32), 256>>>(Wk, b2 + (size_t)2048*K2QKV, HH, 1024, K2QKV);
    split2_transpose<<<dim3(1024/32, HH/32), 256>>>(Wv, b2 + (size_t)3072*K2QKV, HH, 1024, K2QKV);
    gemm_tc<<<dim3(NQKV/128, MROWS/128), 256, GEMM_SMEM>>>(a2, b2, qp, kp, vp, K2QKV, 1, 0);

    // ---- RoPE + fp16 conversions ----
    rope_split_h<<<(BB*NH*SS*128)/256, 256>>>(qp, qh_, ql_, pos, NH, 1.f/(16.f*50.f));
    rope_h<<<(BB*NKV*SS*128)/256, 256>>>(kp, kh_, pos, NKV);
    conv_half<<<(BB*NKV*SS*HD)/256, 256>>>(vp, vh_, BB*NKV*SS*HD);

    // ---- flash attention (fp16 HMMA), epilogue emits out-proj A operand ----
    attn_tc<<<dim3(SS/64, NH, BB), 128, ATT_SMEM>>>(qh_, ql_, kh_, vh_, a2o);

    // ---- out projection ----
    split2_transpose<<<dim3(HH/32, 2048/32), 256>>>(Wo, b2o, 2048, HH, K2O);
    gemm_tc<<<dim3(HH/128, MROWS/128), 256, GEMM_SMEM>>>(a2o, b2o, out, nullptr, nullptr, K2O, 0, HH);
}

// round 8
// speedup vs baseline: 6.5347x; 1.3109x over previous
#include <cuda_runtime.h>
#include <cuda_fp16.h>
#include <cstdint>
#include <math.h>

#define BB   2
#define SS   2048
#define HH   2304
#define NH   8
#define HD   256
#define NKV  4
#define WIN  512
#define MROWS (BB*SS)            // 4096
#define K2O   (2*2048)           // 4096 (O-proj keeps split-2)
#define NQKV  (NH*HD + 2*NKV*HD) // 4096
#define NST   3
#define STAGE_BYTES 32768
#define GEMM_SMEM (NST*STAGE_BYTES + 1024)
#define ATT_SMEM (4*32768 + 1024)   // Qh Ql Kh Vh tiles (32KB each) + align

// ------------------------- device scratch (no allocs allowed) ---------------
__device__ float g_q[(size_t)BB*NH*SS*HD];
__device__ float g_k[(size_t)BB*NKV*SS*HD];
__device__ float g_v[(size_t)BB*NKV*SS*HD];
__device__ __align__(256) __half g_a2 [(size_t)MROWS*HH];    // fp16 activations
__device__ __align__(256) __half g_b2 [(size_t)NQKV*HH];     // fp16 QKV weights (transposed)
__device__ __align__(256) __half g_a2o[(size_t)MROWS*K2O];   // split-2 attention output
__device__ __align__(256) __half g_b2o[(size_t)HH*K2O];      // dup'd Wo fp16
__device__ __align__(256) __half g_qh[(size_t)BB*NH*SS*HD];
__device__ __align__(256) __half g_ql[(size_t)BB*NH*SS*HD];
__device__ __align__(256) __half g_kh[(size_t)BB*NKV*SS*HD];
__device__ __align__(256) __half g_vh[(size_t)BB*NKV*SS*HD];

// ------------------------- PTX helpers --------------------------------------
__device__ __forceinline__ uint32_t smem_u32(const void* p) {
    uint32_t a;
    asm("{ .reg .u64 t; cvta.to.shared.u64 t, %1; cvt.u32.u64 %0, t; }" : "=r"(a) : "l"(p));
    return a;
}
__device__ __forceinline__ uint32_t h2u(__half2 v) {
    return *reinterpret_cast<uint32_t*>(&v);
}
__device__ __forceinline__ void cp_async16(uint32_t saddr, const void* gaddr) {
    asm volatile("cp.async.cg.shared.global [%0], [%1], 16;" :: "r"(saddr), "l"(gaddr) : "memory");
}
__device__ __forceinline__ void cp_commit() {
    asm volatile("cp.async.commit_group;" ::: "memory");
}
__device__ __forceinline__ void cp_wait2() {
    asm volatile("cp.async.wait_group 2;" ::: "memory");
}
__device__ __forceinline__ void cp_wait1() {
    asm volatile("cp.async.wait_group 1;" ::: "memory");
}
__device__ __forceinline__ void ldsm4(uint32_t* r, uint32_t addr) {
    asm volatile("ldmatrix.sync.aligned.m8n8.x4.shared.b16 {%0,%1,%2,%3}, [%4];"
                 : "=r"(r[0]), "=r"(r[1]), "=r"(r[2]), "=r"(r[3]) : "r"(addr));
}
__device__ __forceinline__ void ldsm4t(uint32_t* r, uint32_t addr) {
    asm volatile("ldmatrix.sync.aligned.m8n8.x4.trans.shared.b16 {%0,%1,%2,%3}, [%4];"
                 : "=r"(r[0]), "=r"(r[1]), "=r"(r[2]), "=r"(r[3]) : "r"(addr));
}
__device__ __forceinline__ void mma16816h(float* c, const uint32_t* a, uint32_t b0, uint32_t b1) {
    asm volatile(
        "mma.sync.aligned.m16n8k16.row.col.f32.f16.f16.f32 "
        "{%0,%1,%2,%3}, {%4,%5,%6,%7}, {%8,%9}, {%0,%1,%2,%3};"
        : "+f"(c[0]), "+f"(c[1]), "+f"(c[2]), "+f"(c[3])
        : "r"(a[0]), "r"(a[1]), "r"(a[2]), "r"(a[3]), "r"(b0), "r"(b1));
}
#define SWZ(off) ((off) ^ (((off) >> 3) & 0x70))

__device__ __forceinline__ uint32_t tile_off(int row, int d) {
    uint32_t off = (uint32_t)(row * 128 + (d & 63) * 2);
    return (uint32_t)((d >> 6) * 8192) + SWZ(off);
}

// ------------------------- prep kernels -------------------------------------
// plain fp32 -> fp16 copy (flat)
__global__ __launch_bounds__(256) void conv_half(
    const float* __restrict__ X, __half* __restrict__ Y, int n)
{
    int t = blockIdx.x * blockDim.x + threadIdx.x;
    if (t < n) Y[t] = __float2half(X[t]);
}
// W[K,N] -> Y[n,k] fp16 (transpose + quantize, no duplication)
__global__ __launch_bounds__(256) void transp_h(
    const float* __restrict__ W, __half* __restrict__ Y, int K, int N)
{
    __shared__ float t[32][33];
    int k0 = blockIdx.y * 32, n0 = blockIdx.x * 32;
    int tx = threadIdx.x & 31, ty = threadIdx.x >> 5;
#pragma unroll
    for (int i = 0; i < 4; i++)
        t[ty + i * 8][tx] = W[(size_t)(k0 + ty + i * 8) * N + n0 + tx];
    __syncthreads();
#pragma unroll
    for (int i = 0; i < 4; i++) {
        int n = n0 + ty + i * 8;
        int k = k0 + tx;
        Y[(size_t)n * K + k] = __float2half(t[tx][ty + i * 8]);
    }
}
// W[K,N] -> Y[n, 2k+{0,1}] = {hh, hh}  (transpose + fp16 quantize, dup for split-2 A)
__global__ __launch_bounds__(256) void split2_transpose(
    const float* __restrict__ W, __half* __restrict__ Y, int K, int N, int K2)
{
    __shared__ float t[32][33];
    int k0 = blockIdx.y * 32, n0 = blockIdx.x * 32;
    int tx = threadIdx.x & 31, ty = threadIdx.x >> 5;
#pragma unroll
    for (int i = 0; i < 4; i++)
        t[ty + i * 8][tx] = W[(size_t)(k0 + ty + i * 8) * N + n0 + tx];
    __syncthreads();
#pragma unroll
    for (int i = 0; i < 4; i++) {
        int n = n0 + ty + i * 8;
        int k = k0 + tx;
        __half hh = __float2half(t[tx][ty + i * 8]);
        size_t o = (size_t)n * K2 + 2 * (size_t)k;
        Y[o] = hh; Y[o + 1] = hh;
    }
}

// ------------------------- HMMA GEMM (fp16 operands) ------------------------
__global__ __launch_bounds__(256) void gemm_tc(
    const __half* __restrict__ A2, const __half* __restrict__ B2,
    float* __restrict__ Cq, float* __restrict__ Ck, float* __restrict__ Cv,
    int K2, int mode, int ldN)
{
    extern __shared__ char dsm[];
    const int tid = threadIdx.x;
    const int wid = tid >> 5;
    const int lane = tid & 31;
    const int m0 = blockIdx.y * 128;
    const int n0 = blockIdx.x * 128;
    const int warpM = (wid & 3) * 32;
    const int warpN = (wid >> 2) * 64;

    uint32_t raw = smem_u32(dsm);
    uint32_t sbase = (raw + 1023u) & ~1023u;
    char* dtile = dsm + (sbase - raw);

    const int nk = K2 >> 6;
    const int colb = (tid & 7) * 16;
    const int r0 = tid >> 3;

    float c[2][8][4];
#pragma unroll
    for (int mi = 0; mi < 2; mi++)
#pragma unroll
        for (int nf = 0; nf < 8; nf++)
#pragma unroll
            for (int j = 0; j < 4; j++) c[mi][nf][j] = 0.f;

    const int lrow = lane & 15;
    const int lchunk = (lane >> 4) * 16;

#pragma unroll
    for (int s = 0; s < NST; s++) {
        uint32_t sA = sbase + s * STAGE_BYTES;
        uint32_t sB = sA + 16384;
        int k0 = s * 64;
#pragma unroll
        for (int i = 0; i < 4; i++) {
            int row = i * 32 + r0;
            uint32_t so = SWZ((uint32_t)(row * 128 + colb));
            cp_async16(sA + so, A2 + (size_t)(m0 + row) * K2 + k0 + (tid & 7) * 8);
            cp_async16(sB + so, B2 + (size_t)(n0 + row) * K2 + k0 + (tid & 7) * 8);
        }
        cp_commit();
    }

    for (int ck = 0; ck < nk; ck++) {
        const int s = ck - (ck / NST) * NST;
        cp_wait2();
        __syncthreads();

        uint32_t sA = sbase + s * STAGE_BYTES;
        uint32_t sB = sA + 16384;

#pragma unroll
        for (int ks = 0; ks < 4; ks++) {
            const int kb = ks * 32 + lchunk;
            uint32_t a[2][4], b[4][4];
#pragma unroll
            for (int mi = 0; mi < 2; mi++) {
                int row = warpM + mi * 16 + lrow;
                ldsm4(a[mi], sA + SWZ((uint32_t)(row * 128 + kb)));
            }
#pragma unroll
            for (int ni = 0; ni < 4; ni++) {
                int row = warpN + ni * 16 + lrow;
                ldsm4(b[ni], sB + SWZ((uint32_t)(row * 128 + kb)));
            }
#pragma unroll
            for (int mi = 0; mi < 2; mi++)
#pragma unroll
                for (int ni = 0; ni < 4; ni++) {
                    mma16816h(c[mi][2 * ni + 0], a[mi], b[ni][0], b[ni][2]);
                    mma16816h(c[mi][2 * ni + 1], a[mi], b[ni][1], b[ni][3]);
                }
        }
        __syncthreads();

        const int nck = ck + NST;
        if (nck < nk) {
            int k0 = nck * 64;
#pragma unroll
            for (int i = 0; i < 4; i++) {
                int row = i * 32 + r0;
                uint32_t so = SWZ((uint32_t)(row * 128 + colb));
                cp_async16(sA + so, A2 + (size_t)(m0 + row) * K2 + k0 + (tid & 7) * 8);
                cp_async16(sB + so, B2 + (size_t)(n0 + row) * K2 + k0 + (tid & 7) * 8);
            }
        }
        cp_commit();
    }

    __syncthreads();
    float* stile = (float*)dtile;
    {
        int rquad = lane >> 2;
        int cpair = (lane & 3) << 1;
#pragma unroll
        for (int mi = 0; mi < 2; mi++) {
            int rbase = warpM + mi * 16 + rquad;
#pragma unroll
            for (int nf = 0; nf < 8; nf++) {
                int col = warpN + nf * 8 + cpair;
                *(float2*)&stile[rbase * 132 + col]       = make_float2(c[mi][nf][0], c[mi][nf][1]);
                *(float2*)&stile[(rbase + 8) * 132 + col] = make_float2(c[mi][nf][2], c[mi][nf][3]);
            }
        }
    }
    __syncthreads();

    if (mode == 0) {
#pragma unroll
        for (int i = 0; i < 16; i++) {
            int idx = i * 256 + tid;
            int row = idx >> 5, c4 = idx & 31;
            float4 v = *(float4*)&stile[row * 132 + c4 * 4];
            int m = m0 + row;
            *(float4*)&Cq[(size_t)m * ldN + n0 + c4 * 4] = v;
        }
    } else {
        float* tens; int hh, hp;
        if (n0 < 2048)      { tens = Cq; hh = n0 >> 8;          hp = NH; }
        else if (n0 < 3072) { tens = Ck; hh = (n0 - 2048) >> 8; hp = NKV; }
        else                { tens = Cv; hh = (n0 - 3072) >> 8; hp = NKV; }
        int d0 = n0 & 255;
#pragma unroll
        for (int i = 0; i < 16; i++) {
            int idx = i * 256 + tid;
            int row = idx >> 5, c4 = idx & 31;
            float4 v = *(float4*)&stile[row * 132 + c4 * 4];
            int m = m0 + row;
            int b = m >> 11, sq = m & (SS - 1);
            *(float4*)&tens[(((size_t)(b * hp + hh)) * SS + sq) * HD + d0 + c4 * 4] = v;
        }
    }
}

// --------------- RoPE + fp16 conversions ------------------------------------
__global__ __launch_bounds__(256) void rope_split_h(
    const float* __restrict__ X, __half* __restrict__ Xh, __half* __restrict__ Xl,
    const int* __restrict__ pos_ids, int heads, float scale)
{
    int t = blockIdx.x * blockDim.x + threadIdx.x;
    int d = t & 127;
    int s = (t >> 7) & (SS - 1);
    int rest = t >> 18;
    int hh = rest % heads;
    int b  = rest / heads;
    if (b >= BB) return;
    float p = (float)pos_ids[b * SS + s];
    float inv = powf(10000.f, -(float)d * (1.f / 128.f));
    float ang = p * inv;
    float si, co;
    sincosf(ang, &si, &co);
    size_t base = (((size_t)b * heads + hh) * SS + s) * HD;
    float x1 = X[base + d], x2 = X[base + d + 128];
    float r1 = (x1 * co - x2 * si) * scale;
    float r2 = (x2 * co + x1 * si) * scale;
    __half h1 = __float2half(r1), h2 = __float2half(r2);
    Xh[base + d] = h1;       Xh[base + d + 128] = h2;
    Xl[base + d] = __float2half(r1 - __half2float(h1));
    Xl[base + d + 128] = __float2half(r2 - __half2float(h2));
}
__global__ __launch_bounds__(256) void rope_h(
    const float* __restrict__ X, __half* __restrict__ Xh,
    const int* __restrict__ pos_ids, int heads)
{
    int t = blockIdx.x * blockDim.x + threadIdx.x;
    int d = t & 127;
    int s = (t >> 7) & (SS - 1);
    int rest = t >> 18;
    int hh = rest % heads;
    int b  = rest / heads;
    if (b >= BB) return;
    float p = (float)pos_ids[b * SS + s];
    float inv = powf(10000.f, -(float)d * (1.f / 128.f));
    float ang = p * inv;
    float si, co;
    sincosf(ang, &si, &co);
    size_t base = (((size_t)b * heads + hh) * SS + s) * HD;
    float x1 = X[base + d], x2 = X[base + d + 128];
    Xh[base + d]       = __float2half(x1 * co - x2 * si);
    Xh[base + d + 128] = __float2half(x2 * co + x1 * si);
}

// ------------------------- tensor-core flash attention ----------------------
__device__ __forceinline__ void load_tile_async(uint32_t sdst, const __half* g, int tid) {
#pragma unroll
    for (int i = 0; i < 16; i++) {
        int idx = i * 128 + tid;
        int row = idx >> 5;
        int d = (idx & 31) * 8;
        cp_async16(sdst + tile_off(row, d), g + row * HD + d);
    }
}

__global__ __launch_bounds__(128) void attn_tc(
    const __half* __restrict__ Qh, const __half* __restrict__ Ql,
    const __half* __restrict__ Kh, const __half* __restrict__ Vh,
    __half* __restrict__ A2O)
{
    extern __shared__ char dsm[];
    uint32_t raw = smem_u32(dsm);
    uint32_t sb = (raw + 1023u) & ~1023u;
    const uint32_t sQh = sb, sQl = sb + 32768, sKh = sb + 65536, sVh = sb + 98304;

    const int tid = threadIdx.x;
    const int wid = tid >> 5;
    const int lane = tid & 31;
    const int qblk = blockIdx.x;
    const int h = blockIdx.y;
    const int b = blockIdx.z;
    const int kv = h >> 1;
    const int warpM = wid * 16;

    const __half* qhp = Qh + (((size_t)(b * NH + h)) * SS + qblk * 64) * HD;
    const __half* qlp = Ql + (((size_t)(b * NH + h)) * SS + qblk * 64) * HD;
    const __half* khp = Kh + ((size_t)(b * NKV + kv)) * SS * HD;
    const __half* vhp = Vh + ((size_t)(b * NKV + kv)) * SS * HD;

    int lo = qblk * 64 - (WIN - 1);
    if (lo < 0) lo = 0;
    lo &= ~63;
    const int hi = qblk * 64;

    load_tile_async(sQh, qhp, tid);
    load_tile_async(sQl, qlp, tid);
    load_tile_async(sKh, khp + (size_t)lo * HD, tid);
    cp_commit();
    load_tile_async(sVh, vhp + (size_t)lo * HD, tid);
    cp_commit();

    float oacc[32][4];
#pragma unroll
    for (int i = 0; i < 32; i++)
#pragma unroll
        for (int j = 0; j < 4; j++) oacc[i][j] = 0.f;
    float m0 = -1e30f, m1 = -1e30f, l0 = 0.f, l1 = 0.f;

    const int lrow = lane & 15;
    const int lhalf = (lane >> 4) * 16;
    const int qi = qblk * 64 + warpM + (lane >> 2);

    for (int kt = lo; kt <= hi; kt += 64) {
        cp_wait1();
        __syncthreads();

        float sacc[8][4];
#pragma unroll
        for (int i = 0; i < 8; i++)
#pragma unroll
            for (int j = 0; j < 4; j++) sacc[i][j] = 0.f;

#pragma unroll
        for (int kc = 0; kc < 16; kc++) {
            const int c = kc >> 2;
            const int colb = (kc & 3) * 32 + lhalf;
            uint32_t aqh[4], aql[4];
            uint32_t aoff = (uint32_t)(c * 8192) + SWZ((uint32_t)((warpM + lrow) * 128 + colb));
            ldsm4(aqh, sQh + aoff);
            ldsm4(aql, sQl + aoff);
#pragma unroll
            for (int g = 0; g < 4; g++) {
                uint32_t boff = (uint32_t)(c * 8192) + SWZ((uint32_t)((g * 16 + lrow) * 128 + colb));
                uint32_t bh[4];
                ldsm4(bh, sKh + boff);
                mma16816h(sacc[2 * g],     aqh, bh[0], bh[2]);
                mma16816h(sacc[2 * g + 1], aqh, bh[1], bh[3]);
                mma16816h(sacc[2 * g],     aql, bh[0], bh[2]);
                mma16816h(sacc[2 * g + 1], aql, bh[1], bh[3]);
            }
        }
        __syncthreads();
        if (kt + 64 <= hi)
            load_tile_async(sKh, khp + (size_t)(kt + 64) * HD, tid);
        cp_commit();

        float tm0 = -1e30f, tm1 = -1e30f;
#pragma unroll
        for (int nt = 0; nt < 8; nt++) {
#pragma unroll
            for (int j = 0; j < 4; j++) {
                int kj = kt + nt * 8 + (lane & 3) * 2 + (j & 1);
                int row = qi + ((j >> 1) * 8);
                float x = sacc[nt][j];
                float e = __expf(2.f * x);
                float s = 50.f * __fdividef(e - 1.f, e + 1.f);
                bool ok = (kj <= row) && (row - kj < WIN);
                s = ok ? s : -1e30f;
                sacc[nt][j] = s;
                if (j < 2) tm0 = fmaxf(tm0, s); else tm1 = fmaxf(tm1, s);
            }
        }
        tm0 = fmaxf(tm0, __shfl_xor_sync(0xffffffffu, tm0, 1));
        tm0 = fmaxf(tm0, __shfl_xor_sync(0xffffffffu, tm0, 2));
        tm1 = fmaxf(tm1, __shfl_xor_sync(0xffffffffu, tm1, 1));
        tm1 = fmaxf(tm1, __shfl_xor_sync(0xffffffffu, tm1, 2));

        float mn0 = fmaxf(m0, tm0), mn1 = fmaxf(m1, tm1);
        float al0 = __expf(m0 - mn0), al1 = __expf(m1 - mn1);
        m0 = mn0; m1 = mn1;

        float rs0 = 0.f, rs1 = 0.f;
#pragma unroll
        for (int nt = 0; nt < 8; nt++) {
            float p0 = __expf(sacc[nt][0] - mn0);
            float p1 = __expf(sacc[nt][1] - mn0);
            float p2 = __expf(sacc[nt][2] - mn1);
            float p3 = __expf(sacc[nt][3] - mn1);
            sacc[nt][0] = p0; sacc[nt][1] = p1; sacc[nt][2] = p2; sacc[nt][3] = p3;
            rs0 += p0 + p1; rs1 += p2 + p3;
        }
        rs0 += __shfl_xor_sync(0xffffffffu, rs0, 1);
        rs0 += __shfl_xor_sync(0xffffffffu, rs0, 2);
        rs1 += __shfl_xor_sync(0xffffffffu, rs1, 1);
        rs1 += __shfl_xor_sync(0xffffffffu, rs1, 2);
        l0 = l0 * al0 + rs0;
        l1 = l1 * al1 + rs1;

        uint32_t aP[4][4];
#pragma unroll
        for (int kc2 = 0; kc2 < 4; kc2++) {
            aP[kc2][0] = h2u(__floats2half2_rn(sacc[2 * kc2][0],     sacc[2 * kc2][1]));
            aP[kc2][1] = h2u(__floats2half2_rn(sacc[2 * kc2][2],     sacc[2 * kc2][3]));
            aP[kc2][2] = h2u(__floats2half2_rn(sacc[2 * kc2 + 1][0], sacc[2 * kc2 + 1][1]));
            aP[kc2][3] = h2u(__floats2half2_rn(sacc[2 * kc2 + 1][2], sacc[2 * kc2 + 1][3]));
        }

#pragma unroll
        for (int dt = 0; dt < 32; dt++) {
            oacc[dt][0] *= al0; oacc[dt][1] *= al0;
            oacc[dt][2] *= al1; oacc[dt][3] *= al1;
        }

        cp_wait1();
        __syncthreads();

#pragma unroll
        for (int kc2 = 0; kc2 < 4; kc2++) {
#pragma unroll
            for (int dg = 0; dg < 16; dg++) {
                int key = kc2 * 16 + lrow;
                int d = dg * 16 + (lane >> 4) * 8;
                uint32_t r[4];
                ldsm4t(r, sVh + tile_off(key, d));
                mma16816h(oacc[dg * 2],     aP[kc2], r[0], r[1]);
                mma16816h(oacc[dg * 2 + 1], aP[kc2], r[2], r[3]);
            }
        }
        __syncthreads();
        if (kt + 64 <= hi)
            load_tile_async(sVh, vhp + (size_t)(kt + 64) * HD, tid);
        cp_commit();
    }

    // ---- epilogue: write split-2 fp16 directly into out-proj A buffer ----
    float il0 = __fdividef(1.f, l0);
    float il1 = __fdividef(1.f, l1);
    __half* a0 = A2O + ((size_t)(b * SS + qi)) * K2O + 2 * (h * HD);
    __half* a1 = A2O + ((size_t)(b * SS + qi + 8)) * K2O + 2 * (h * HD);
    int cbase = (lane & 3) * 2;
#pragma unroll
    for (int dt = 0; dt < 32; dt++) {
        int col = dt * 8 + cbase;
        float v0 = oacc[dt][0] * il0, v1 = oacc[dt][1] * il0;
        float v2 = oacc[dt][2] * il1, v3 = oacc[dt][3] * il1;
        __half h0 = __float2half(v0), h1v = __float2half(v1);
        __half h2v = __float2half(v2), h3 = __float2half(v3);
        __half2 p0 = __halves2half2(h0, __float2half(v0 - __half2float(h0)));
        __half2 p1 = __halves2half2(h1v, __float2half(v1 - __half2float(h1v)));
        __half2 p2 = __halves2half2(h2v, __float2half(v2 - __half2float(h2v)));
        __half2 p3 = __halves2half2(h3, __float2half(v3 - __half2float(h3)));
        *(__half2*)&a0[2 * col]     = p0;
        *(__half2*)&a0[2 * col + 2] = p1;
        *(__half2*)&a1[2 * col]     = p2;
        *(__half2*)&a1[2 * col + 2] = p3;
    }
}

// ---------------------------------------------------------------------------
extern "C" void kernel_launch(void* const* d_in, const int* in_sizes, int n_in,
                              void* d_out, int out_size)
{
    const float* hid = (const float*)d_in[0];
    const int*   pos = (const int*)d_in[2];
    const float* Wq  = (const float*)d_in[3];
    const float* Wk  = (const float*)d_in[4];
    const float* Wv  = (const float*)d_in[5];
    const float* Wo  = (const float*)d_in[6];
    float* out = (float*)d_out;

    float *qp, *kp, *vp;
    __half *a2, *b2, *a2o, *b2o, *qh_, *ql_, *kh_, *vh_;
    cudaGetSymbolAddress((void**)&qp,  g_q);
    cudaGetSymbolAddress((void**)&kp,  g_k);
    cudaGetSymbolAddress((void**)&vp,  g_v);
    cudaGetSymbolAddress((void**)&a2,  g_a2);
    cudaGetSymbolAddress((void**)&b2,  g_b2);
    cudaGetSymbolAddress((void**)&a2o, g_a2o);
    cudaGetSymbolAddress((void**)&b2o, g_b2o);
    cudaGetSymbolAddress((void**)&qh_, g_qh);
    cudaGetSymbolAddress((void**)&ql_, g_ql);
    cudaGetSymbolAddress((void**)&kh_, g_kh);
    cudaGetSymbolAddress((void**)&vh_, g_vh);

    cudaFuncSetAttribute(gemm_tc, cudaFuncAttributeMaxDynamicSharedMemorySize, GEMM_SMEM);
    cudaFuncSetAttribute(attn_tc, cudaFuncAttributeMaxDynamicSharedMemorySize, ATT_SMEM);

    // ---- QKV projections: plain fp16 A, fp16 W, K=2304 ----
    conv_half<<<(MROWS*HH + 255)/256, 256>>>(hid, a2, MROWS*HH);
    transp_h<<<dim3(2048/32, HH/32), 256>>>(Wq, b2, HH, 2048);
    transp_h<<<dim3(1024/32, HH/32), 256>>>(Wk, b2 + (size_t)2048*HH, HH, 1024);
    transp_h<<<dim3(1024/32, HH/32), 256>>>(Wv, b2 + (size_t)3072*HH, HH, 1024);
    gemm_tc<<<dim3(NQKV/128, MROWS/128), 256, GEMM_SMEM>>>(a2, b2, qp, kp, vp, HH, 1, 0);

    // ---- RoPE + fp16 conversions ----
    rope_split_h<<<(BB*NH*SS*128)/256, 256>>>(qp, qh_, ql_, pos, NH, 1.f/(16.f*50.f));
    rope_h<<<(BB*NKV*SS*128)/256, 256>>>(kp, kh_, pos, NKV);
    conv_half<<<(BB*NKV*SS*HD)/256, 256>>>(vp, vh_, BB*NKV*SS*HD);

    // ---- flash attention (fp16 HMMA), epilogue emits out-proj A operand ----
    attn_tc<<<dim3(SS/64, NH, BB), 128, ATT_SMEM>>>(qh_, ql_, kh_, vh_, a2o);

    // ---- out projection (split-2) ----
    split2_transpose<<<dim3(HH/32, 2048/32), 256>>>(Wo, b2o, 2048, HH, K2O);
    gemm_tc<<<dim3(HH/128, MROWS/128), 256, GEMM_SMEM>>>(a2o, b2o, out, nullptr, nullptr, K2O, 0, HH);
}

// round 9
// speedup vs baseline: 8.0783x; 1.2362x over previous
#include <cuda_runtime.h>
#include <cuda_fp16.h>
#include <cstdint>
#include <math.h>

#define BB   2
#define SS   2048
#define HH   2304
#define NH   8
#define HD   256
#define NKV  4
#define WIN  512
#define MROWS (BB*SS)            // 4096
#define KO   2048                // O-proj K (plain fp16, no split)
#define NQKV (NH*HD + 2*NKV*HD)  // 4096
#define NST   3
#define STAGE_BYTES 32768
#define GEMM_SMEM (NST*STAGE_BYTES + 1024)
#define ATT_SMEM (4*32768 + 1024)   // Qh Ql Kh Vh tiles (32KB each) + align

// ------------------------- device scratch (no allocs allowed) ---------------
__device__ float g_q[(size_t)BB*NH*SS*HD];
__device__ float g_k[(size_t)BB*NKV*SS*HD];
__device__ __align__(256) __half g_a2 [(size_t)MROWS*HH];    // fp16 activations
__device__ __align__(256) __half g_b2 [(size_t)NQKV*HH];     // fp16 QKV weights (transposed)
__device__ __align__(256) __half g_a2o[(size_t)MROWS*KO];    // fp16 attention output
__device__ __align__(256) __half g_b2o[(size_t)HH*KO];       // fp16 Wo (transposed)
__device__ __align__(256) __half g_qh[(size_t)BB*NH*SS*HD];
__device__ __align__(256) __half g_ql[(size_t)BB*NH*SS*HD];
__device__ __align__(256) __half g_kh[(size_t)BB*NKV*SS*HD];
__device__ __align__(256) __half g_vh[(size_t)BB*NKV*SS*HD];

// ------------------------- PTX helpers --------------------------------------
__device__ __forceinline__ uint32_t smem_u32(const void* p) {
    uint32_t a;
    asm("{ .reg .u64 t; cvta.to.shared.u64 t, %1; cvt.u32.u64 %0, t; }" : "=r"(a) : "l"(p));
    return a;
}
__device__ __forceinline__ uint32_t h2u(__half2 v) {
    return *reinterpret_cast<uint32_t*>(&v);
}
__device__ __forceinline__ void cp_async16(uint32_t saddr, const void* gaddr) {
    asm volatile("cp.async.cg.shared.global [%0], [%1], 16;" :: "r"(saddr), "l"(gaddr) : "memory");
}
__device__ __forceinline__ void cp_commit() {
    asm volatile("cp.async.commit_group;" ::: "memory");
}
__device__ __forceinline__ void cp_wait2() {
    asm volatile("cp.async.wait_group 2;" ::: "memory");
}
__device__ __forceinline__ void cp_wait1() {
    asm volatile("cp.async.wait_group 1;" ::: "memory");
}
__device__ __forceinline__ void ldsm4(uint32_t* r, uint32_t addr) {
    asm volatile("ldmatrix.sync.aligned.m8n8.x4.shared.b16 {%0,%1,%2,%3}, [%4];"
                 : "=r"(r[0]), "=r"(r[1]), "=r"(r[2]), "=r"(r[3]) : "r"(addr));
}
__device__ __forceinline__ void ldsm4t(uint32_t* r, uint32_t addr) {
    asm volatile("ldmatrix.sync.aligned.m8n8.x4.trans.shared.b16 {%0,%1,%2,%3}, [%4];"
                 : "=r"(r[0]), "=r"(r[1]), "=r"(r[2]), "=r"(r[3]) : "r"(addr));
}
__device__ __forceinline__ void mma16816h(float* c, const uint32_t* a, uint32_t b0, uint32_t b1) {
    asm volatile(
        "mma.sync.aligned.m16n8k16.row.col.f32.f16.f16.f32 "
        "{%0,%1,%2,%3}, {%4,%5,%6,%7}, {%8,%9}, {%0,%1,%2,%3};"
        : "+f"(c[0]), "+f"(c[1]), "+f"(c[2]), "+f"(c[3])
        : "r"(a[0]), "r"(a[1]), "r"(a[2]), "r"(a[3]), "r"(b0), "r"(b1));
}
#define SWZ(off) ((off) ^ (((off) >> 3) & 0x70))

__device__ __forceinline__ uint32_t tile_off(int row, int d) {
    uint32_t off = (uint32_t)(row * 128 + (d & 63) * 2);
    return (uint32_t)((d >> 6) * 8192) + SWZ(off);
}

// ------------------------- prep kernels -------------------------------------
__global__ __launch_bounds__(256) void conv_half(
    const float* __restrict__ X, __half* __restrict__ Y, int n)
{
    int t = blockIdx.x * blockDim.x + threadIdx.x;
    if (t < n) Y[t] = __float2half(X[t]);
}
// W[K,N] -> Y[n,k] fp16 (transpose + quantize)
__global__ __launch_bounds__(256) void transp_h(
    const float* __restrict__ W, __half* __restrict__ Y, int K, int N)
{
    __shared__ float t[32][33];
    int k0 = blockIdx.y * 32, n0 = blockIdx.x * 32;
    int tx = threadIdx.x & 31, ty = threadIdx.x >> 5;
#pragma unroll
    for (int i = 0; i < 4; i++)
        t[ty + i * 8][tx] = W[(size_t)(k0 + ty + i * 8) * N + n0 + tx];
    __syncthreads();
#pragma unroll
    for (int i = 0; i < 4; i++) {
        int n = n0 + ty + i * 8;
        int k = k0 + tx;
        Y[(size_t)n * K + k] = __float2half(t[tx][ty + i * 8]);
    }
}

// ------------------------- HMMA GEMM (fp16 operands) ------------------------
// mode 0: C fp32 row-major (ldN). mode 1: QKV scatter — q,k fp32 head-major
// (need RoPE), v fp16 head-major direct.
__global__ __launch_bounds__(256) void gemm_tc(
    const __half* __restrict__ A2, const __half* __restrict__ B2,
    float* __restrict__ Cq, float* __restrict__ Ck, __half* __restrict__ Cv,
    int K2, int mode, int ldN)
{
    extern __shared__ char dsm[];
    const int tid = threadIdx.x;
    const int wid = tid >> 5;
    const int lane = tid & 31;
    const int m0 = blockIdx.y * 128;
    const int n0 = blockIdx.x * 128;
    const int warpM = (wid & 3) * 32;
    const int warpN = (wid >> 2) * 64;

    uint32_t raw = smem_u32(dsm);
    uint32_t sbase = (raw + 1023u) & ~1023u;
    char* dtile = dsm + (sbase - raw);

    const int nk = K2 >> 6;
    const int colb = (tid & 7) * 16;
    const int r0 = tid >> 3;

    float c[2][8][4];
#pragma unroll
    for (int mi = 0; mi < 2; mi++)
#pragma unroll
        for (int nf = 0; nf < 8; nf++)
#pragma unroll
            for (int j = 0; j < 4; j++) c[mi][nf][j] = 0.f;

    const int lrow = lane & 15;
    const int lchunk = (lane >> 4) * 16;

#pragma unroll
    for (int s = 0; s < NST; s++) {
        uint32_t sA = sbase + s * STAGE_BYTES;
        uint32_t sB = sA + 16384;
        int k0 = s * 64;
#pragma unroll
        for (int i = 0; i < 4; i++) {
            int row = i * 32 + r0;
            uint32_t so = SWZ((uint32_t)(row * 128 + colb));
            cp_async16(sA + so, A2 + (size_t)(m0 + row) * K2 + k0 + (tid & 7) * 8);
            cp_async16(sB + so, B2 + (size_t)(n0 + row) * K2 + k0 + (tid & 7) * 8);
        }
        cp_commit();
    }

    for (int ck = 0; ck < nk; ck++) {
        const int s = ck - (ck / NST) * NST;
        cp_wait2();
        __syncthreads();

        uint32_t sA = sbase + s * STAGE_BYTES;
        uint32_t sB = sA + 16384;

#pragma unroll
        for (int ks = 0; ks < 4; ks++) {
            const int kb = ks * 32 + lchunk;
            uint32_t a[2][4], b[4][4];
#pragma unroll
            for (int mi = 0; mi < 2; mi++) {
                int row = warpM + mi * 16 + lrow;
                ldsm4(a[mi], sA + SWZ((uint32_t)(row * 128 + kb)));
            }
#pragma unroll
            for (int ni = 0; ni < 4; ni++) {
                int row = warpN + ni * 16 + lrow;
                ldsm4(b[ni], sB + SWZ((uint32_t)(row * 128 + kb)));
            }
#pragma unroll
            for (int mi = 0; mi < 2; mi++)
#pragma unroll
                for (int ni = 0; ni < 4; ni++) {
                    mma16816h(c[mi][2 * ni + 0], a[mi], b[ni][0], b[ni][2]);
                    mma16816h(c[mi][2 * ni + 1], a[mi], b[ni][1], b[ni][3]);
                }
        }
        __syncthreads();

        const int nck = ck + NST;
        if (nck < nk) {
            int k0 = nck * 64;
#pragma unroll
            for (int i = 0; i < 4; i++) {
                int row = i * 32 + r0;
                uint32_t so = SWZ((uint32_t)(row * 128 + colb));
                cp_async16(sA + so, A2 + (size_t)(m0 + row) * K2 + k0 + (tid & 7) * 8);
                cp_async16(sB + so, B2 + (size_t)(n0 + row) * K2 + k0 + (tid & 7) * 8);
            }
        }
        cp_commit();
    }

    __syncthreads();
    float* stile = (float*)dtile;
    {
        int rquad = lane >> 2;
        int cpair = (lane & 3) << 1;
#pragma unroll
        for (int mi = 0; mi < 2; mi++) {
            int rbase = warpM + mi * 16 + rquad;
#pragma unroll
            for (int nf = 0; nf < 8; nf++) {
                int col = warpN + nf * 8 + cpair;
                *(float2*)&stile[rbase * 132 + col]       = make_float2(c[mi][nf][0], c[mi][nf][1]);
                *(float2*)&stile[(rbase + 8) * 132 + col] = make_float2(c[mi][nf][2], c[mi][nf][3]);
            }
        }
    }
    __syncthreads();

    if (mode == 0) {
#pragma unroll
        for (int i = 0; i < 16; i++) {
            int idx = i * 256 + tid;
            int row = idx >> 5, c4 = idx & 31;
            float4 v = *(float4*)&stile[row * 132 + c4 * 4];
            int m = m0 + row;
            *(float4*)&Cq[(size_t)m * ldN + n0 + c4 * 4] = v;
        }
    } else if (n0 < 3072) {
        // Q or K region: fp32 head-major (RoPE consumes fp32)
        float* tens; int hh, hp;
        if (n0 < 2048) { tens = Cq; hh = n0 >> 8;          hp = NH; }
        else           { tens = Ck; hh = (n0 - 2048) >> 8; hp = NKV; }
        int d0 = n0 & 255;
#pragma unroll
        for (int i = 0; i < 16; i++) {
            int idx = i * 256 + tid;
            int row = idx >> 5, c4 = idx & 31;
            float4 v = *(float4*)&stile[row * 132 + c4 * 4];
            int m = m0 + row;
            int b = m >> 11, sq = m & (SS - 1);
            *(float4*)&tens[(((size_t)(b * hp + hh)) * SS + sq) * HD + d0 + c4 * 4] = v;
        }
    } else {
        // V region: write fp16 head-major directly (no RoPE needed)
        int hh = (n0 - 3072) >> 8;
        int d0 = n0 & 255;
#pragma unroll
        for (int i = 0; i < 16; i++) {
            int idx = i * 256 + tid;
            int row = idx >> 5, c4 = idx & 31;
            float4 v = *(float4*)&stile[row * 132 + c4 * 4];
            int m = m0 + row;
            int b = m >> 11, sq = m & (SS - 1);
            __half* dst = Cv + (((size_t)(b * NKV + hh)) * SS + sq) * HD + d0 + c4 * 4;
            *(__half2*)&dst[0] = __floats2half2_rn(v.x, v.y);
            *(__half2*)&dst[2] = __floats2half2_rn(v.z, v.w);
        }
    }
}

// --------------- RoPE + fp16 conversions ------------------------------------
__global__ __launch_bounds__(256) void rope_split_h(
    const float* __restrict__ X, __half* __restrict__ Xh, __half* __restrict__ Xl,
    const int* __restrict__ pos_ids, int heads, float scale)
{
    int t = blockIdx.x * blockDim.x + threadIdx.x;
    int d = t & 127;
    int s = (t >> 7) & (SS - 1);
    int rest = t >> 18;
    int hh = rest % heads;
    int b  = rest / heads;
    if (b >= BB) return;
    float p = (float)pos_ids[b * SS + s];
    float inv = powf(10000.f, -(float)d * (1.f / 128.f));
    float ang = p * inv;
    float si, co;
    sincosf(ang, &si, &co);
    size_t base = (((size_t)b * heads + hh) * SS + s) * HD;
    float x1 = X[base + d], x2 = X[base + d + 128];
    float r1 = (x1 * co - x2 * si) * scale;
    float r2 = (x2 * co + x1 * si) * scale;
    __half h1 = __float2half(r1), h2 = __float2half(r2);
    Xh[base + d] = h1;       Xh[base + d + 128] = h2;
    Xl[base + d] = __float2half(r1 - __half2float(h1));
    Xl[base + d + 128] = __float2half(r2 - __half2float(h2));
}
__global__ __launch_bounds__(256) void rope_h(
    const float* __restrict__ X, __half* __restrict__ Xh,
    const int* __restrict__ pos_ids, int heads)
{
    int t = blockIdx.x * blockDim.x + threadIdx.x;
    int d = t & 127;
    int s = (t >> 7) & (SS - 1);
    int rest = t >> 18;
    int hh = rest % heads;
    int b  = rest / heads;
    if (b >= BB) return;
    float p = (float)pos_ids[b * SS + s];
    float inv = powf(10000.f, -(float)d * (1.f / 128.f));
    float ang = p * inv;
    float si, co;
    sincosf(ang, &si, &co);
    size_t base = (((size_t)b * heads + hh) * SS + s) * HD;
    float x1 = X[base + d], x2 = X[base + d + 128];
    Xh[base + d]       = __float2half(x1 * co - x2 * si);
    Xh[base + d + 128] = __float2half(x2 * co + x1 * si);
}

// ------------------------- tensor-core flash attention ----------------------
__device__ __forceinline__ void load_tile_async(uint32_t sdst, const __half* g, int tid) {
#pragma unroll
    for (int i = 0; i < 16; i++) {
        int idx = i * 128 + tid;
        int row = idx >> 5;
        int d = (idx & 31) * 8;
        cp_async16(sdst + tile_off(row, d), g + row * HD + d);
    }
}

__global__ __launch_bounds__(128) void attn_tc(
    const __half* __restrict__ Qh, const __half* __restrict__ Ql,
    const __half* __restrict__ Kh, const __half* __restrict__ Vh,
    __half* __restrict__ A2O)
{
    extern __shared__ char dsm[];
    uint32_t raw = smem_u32(dsm);
    uint32_t sb = (raw + 1023u) & ~1023u;
    const uint32_t sQh = sb, sQl = sb + 32768, sKh = sb + 65536, sVh = sb + 98304;

    const int tid = threadIdx.x;
    const int wid = tid >> 5;
    const int lane = tid & 31;
    const int qblk = blockIdx.x;
    const int h = blockIdx.y;
    const int b = blockIdx.z;
    const int kv = h >> 1;
    const int warpM = wid * 16;

    const __half* qhp = Qh + (((size_t)(b * NH + h)) * SS + qblk * 64) * HD;
    const __half* qlp = Ql + (((size_t)(b * NH + h)) * SS + qblk * 64) * HD;
    const __half* khp = Kh + ((size_t)(b * NKV + kv)) * SS * HD;
    const __half* vhp = Vh + ((size_t)(b * NKV + kv)) * SS * HD;

    int lo = qblk * 64 - (WIN - 1);
    if (lo < 0) lo = 0;
    lo &= ~63;
    const int hi = qblk * 64;

    load_tile_async(sQh, qhp, tid);
    load_tile_async(sQl, qlp, tid);
    load_tile_async(sKh, khp + (size_t)lo * HD, tid);
    cp_commit();
    load_tile_async(sVh, vhp + (size_t)lo * HD, tid);
    cp_commit();

    float oacc[32][4];
#pragma unroll
    for (int i = 0; i < 32; i++)
#pragma unroll
        for (int j = 0; j < 4; j++) oacc[i][j] = 0.f;
    float m0 = -1e30f, m1 = -1e30f, l0 = 0.f, l1 = 0.f;

    const int lrow = lane & 15;
    const int lhalf = (lane >> 4) * 16;
    const int qi = qblk * 64 + warpM + (lane >> 2);

    for (int kt = lo; kt <= hi; kt += 64) {
        cp_wait1();
        __syncthreads();

        float sacc[8][4];
#pragma unroll
        for (int i = 0; i < 8; i++)
#pragma unroll
            for (int j = 0; j < 4; j++) sacc[i][j] = 0.f;

#pragma unroll
        for (int kc = 0; kc < 16; kc++) {
            const int c = kc >> 2;
            const int colb = (kc & 3) * 32 + lhalf;
            uint32_t aqh[4], aql[4];
            uint32_t aoff = (uint32_t)(c * 8192) + SWZ((uint32_t)((warpM + lrow) * 128 + colb));
            ldsm4(aqh, sQh + aoff);
            ldsm4(aql, sQl + aoff);
#pragma unroll
            for (int g = 0; g < 4; g++) {
                uint32_t boff = (uint32_t)(c * 8192) + SWZ((uint32_t)((g * 16 + lrow) * 128 + colb));
                uint32_t bh[4];
                ldsm4(bh, sKh + boff);
                mma16816h(sacc[2 * g],     aqh, bh[0], bh[2]);
                mma16816h(sacc[2 * g + 1], aqh, bh[1], bh[3]);
                mma16816h(sacc[2 * g],     aql, bh[0], bh[2]);
                mma16816h(sacc[2 * g + 1], aql, bh[1], bh[3]);
            }
        }
        __syncthreads();
        if (kt + 64 <= hi)
            load_tile_async(sKh, khp + (size_t)(kt + 64) * HD, tid);
        cp_commit();

        float tm0 = -1e30f, tm1 = -1e30f;
#pragma unroll
        for (int nt = 0; nt < 8; nt++) {
#pragma unroll
            for (int j = 0; j < 4; j++) {
                int kj = kt + nt * 8 + (lane & 3) * 2 + (j & 1);
                int row = qi + ((j >> 1) * 8);
                float x = sacc[nt][j];
                float e = __expf(2.f * x);
                float s = 50.f * __fdividef(e - 1.f, e + 1.f);
                bool ok = (kj <= row) && (row - kj < WIN);
                s = ok ? s : -1e30f;
                sacc[nt][j] = s;
                if (j < 2) tm0 = fmaxf(tm0, s); else tm1 = fmaxf(tm1, s);
            }
        }
        tm0 = fmaxf(tm0, __shfl_xor_sync(0xffffffffu, tm0, 1));
        tm0 = fmaxf(tm0, __shfl_xor_sync(0xffffffffu, tm0, 2));
        tm1 = fmaxf(tm1, __shfl_xor_sync(0xffffffffu, tm1, 1));
        tm1 = fmaxf(tm1, __shfl_xor_sync(0xffffffffu, tm1, 2));

        float mn0 = fmaxf(m0, tm0), mn1 = fmaxf(m1, tm1);
        float al0 = __expf(m0 - mn0), al1 = __expf(m1 - mn1);
        m0 = mn0; m1 = mn1;

        float rs0 = 0.f, rs1 = 0.f;
#pragma unroll
        for (int nt = 0; nt < 8; nt++) {
            float p0 = __expf(sacc[nt][0] - mn0);
            float p1 = __expf(sacc[nt][1] - mn0);
            float p2 = __expf(sacc[nt][2] - mn1);
            float p3 = __expf(sacc[nt][3] - mn1);
            sacc[nt][0] = p0; sacc[nt][1] = p1; sacc[nt][2] = p2; sacc[nt][3] = p3;
            rs0 += p0 + p1; rs1 += p2 + p3;
        }
        rs0 += __shfl_xor_sync(0xffffffffu, rs0, 1);
        rs0 += __shfl_xor_sync(0xffffffffu, rs0, 2);
        rs1 += __shfl_xor_sync(0xffffffffu, rs1, 1);
        rs1 += __shfl_xor_sync(0xffffffffu, rs1, 2);
        l0 = l0 * al0 + rs0;
        l1 = l1 * al1 + rs1;

        uint32_t aP[4][4];
#pragma unroll
        for (int kc2 = 0; kc2 < 4; kc2++) {
            aP[kc2][0] = h2u(__floats2half2_rn(sacc[2 * kc2][0],     sacc[2 * kc2][1]));
            aP[kc2][1] = h2u(__floats2half2_rn(sacc[2 * kc2][2],     sacc[2 * kc2][3]));
            aP[kc2][2] = h2u(__floats2half2_rn(sacc[2 * kc2 + 1][0], sacc[2 * kc2 + 1][1]));
            aP[kc2][3] = h2u(__floats2half2_rn(sacc[2 * kc2 + 1][2], sacc[2 * kc2 + 1][3]));
        }

#pragma unroll
        for (int dt = 0; dt < 32; dt++) {
            oacc[dt][0] *= al0; oacc[dt][1] *= al0;
            oacc[dt][2] *= al1; oacc[dt][3] *= al1;
        }

        cp_wait1();
        __syncthreads();

#pragma unroll
        for (int kc2 = 0; kc2 < 4; kc2++) {
#pragma unroll
            for (int dg = 0; dg < 16; dg++) {
                int key = kc2 * 16 + lrow;
                int d = dg * 16 + (lane >> 4) * 8;
                uint32_t r[4];
                ldsm4t(r, sVh + tile_off(key, d));
                mma16816h(oacc[dg * 2],     aP[kc2], r[0], r[1]);
                mma16816h(oacc[dg * 2 + 1], aP[kc2], r[2], r[3]);
            }
        }
        __syncthreads();
        if (kt + 64 <= hi)
            load_tile_async(sVh, vhp + (size_t)(kt + 64) * HD, tid);
        cp_commit();
    }

    // ---- epilogue: plain fp16 into out-proj A buffer (K = 2048) ----
    float il0 = __fdividef(1.f, l0);
    float il1 = __fdividef(1.f, l1);
    __half* a0 = A2O + ((size_t)(b * SS + qi)) * KO + h * HD;
    __half* a1 = A2O + ((size_t)(b * SS + qi + 8)) * KO + h * HD;
    int cbase = (lane & 3) * 2;
#pragma unroll
    for (int dt = 0; dt < 32; dt++) {
        int col = dt * 8 + cbase;
        *(__half2*)&a0[col] = __floats2half2_rn(oacc[dt][0] * il0, oacc[dt][1] * il0);
        *(__half2*)&a1[col] = __floats2half2_rn(oacc[dt][2] * il1, oacc[dt][3] * il1);
    }
}

// ---------------------------------------------------------------------------
extern "C" void kernel_launch(void* const* d_in, const int* in_sizes, int n_in,
                              void* d_out, int out_size)
{
    const float* hid = (const float*)d_in[0];
    const int*   pos = (const int*)d_in[2];
    const float* Wq  = (const float*)d_in[3];
    const float* Wk  = (const float*)d_in[4];
    const float* Wv  = (const float*)d_in[5];
    const float* Wo  = (const float*)d_in[6];
    float* out = (float*)d_out;

    float *qp, *kp;
    __half *a2, *b2, *a2o, *b2o, *qh_, *ql_, *kh_, *vh_;
    cudaGetSymbolAddress((void**)&qp,  g_q);
    cudaGetSymbolAddress((void**)&kp,  g_k);
    cudaGetSymbolAddress((void**)&a2,  g_a2);
    cudaGetSymbolAddress((void**)&b2,  g_b2);
    cudaGetSymbolAddress((void**)&a2o, g_a2o);
    cudaGetSymbolAddress((void**)&b2o, g_b2o);
    cudaGetSymbolAddress((void**)&qh_, g_qh);
    cudaGetSymbolAddress((void**)&ql_, g_ql);
    cudaGetSymbolAddress((void**)&kh_, g_kh);
    cudaGetSymbolAddress((void**)&vh_, g_vh);

    cudaFuncSetAttribute(gemm_tc, cudaFuncAttributeMaxDynamicSharedMemorySize, GEMM_SMEM);
    cudaFuncSetAttribute(attn_tc, cudaFuncAttributeMaxDynamicSharedMemorySize, ATT_SMEM);

    // ---- QKV projections: plain fp16 A, fp16 W, K=2304 ----
    conv_half<<<(MROWS*HH + 255)/256, 256>>>(hid, a2, MROWS*HH);
    transp_h<<<dim3(2048/32, HH/32), 256>>>(Wq, b2, HH, 2048);
    transp_h<<<dim3(1024/32, HH/32), 256>>>(Wk, b2 + (size_t)2048*HH, HH, 1024);
    transp_h<<<dim3(1024/32, HH/32), 256>>>(Wv, b2 + (size_t)3072*HH, HH, 1024);
    gemm_tc<<<dim3(NQKV/128, MROWS/128), 256, GEMM_SMEM>>>(a2, b2, qp, kp, vh_, HH, 1, 0);

    // ---- RoPE + fp16 conversions ----
    rope_split_h<<<(BB*NH*SS*128)/256, 256>>>(qp, qh_, ql_, pos, NH, 1.f/(16.f*50.f));
    rope_h<<<(BB*NKV*SS*128)/256, 256>>>(kp, kh_, pos, NKV);

    // ---- flash attention (fp16 HMMA), epilogue emits out-proj A operand ----
    attn_tc<<<dim3(SS/64, NH, BB), 128, ATT_SMEM>>>(qh_, ql_, kh_, vh_, a2o);

    // ---- out projection (plain fp16, K=2048) ----
    transp_h<<<dim3(HH/32, 2048/32), 256>>>(Wo, b2o, 2048, HH);
    gemm_tc<<<dim3(HH/128, MROWS/128), 256, GEMM_SMEM>>>(a2o, b2o, out, nullptr, nullptr, KO, 0, HH);
}

// round 10
// speedup vs baseline: 8.2687x; 1.0236x over previous
#include <cuda_runtime.h>
#include <cuda_fp16.h>
#include <cstdint>
#include <math.h>

#define BB   2
#define SS   2048
#define HH   2304
#define NH   8
#define HD   256
#define NKV  4
#define WIN  512
#define MROWS (BB*SS)            // 4096
#define KO   2048                // O-proj K (plain fp16)
#define NQKV (NH*HD + 2*NKV*HD)  // 4096
#define NST   3
#define STAGE_BYTES 32768
#define GEMM_SMEM (NST*STAGE_BYTES + 1024)
#define ATT_SMEM (4*32768 + 1024)

// ------------------------- device scratch (no allocs allowed) ---------------
__device__ float g_q[(size_t)BB*NH*SS*HD];
__device__ float g_k[(size_t)BB*NKV*SS*HD];
__device__ __align__(256) __half g_a2 [(size_t)MROWS*HH];
__device__ __align__(256) __half g_b2 [(size_t)NQKV*HH];
__device__ __align__(256) __half g_a2o[(size_t)MROWS*KO];
__device__ __align__(256) __half g_b2o[(size_t)HH*KO];
__device__ __align__(256) __half g_qh[(size_t)BB*NH*SS*HD];
__device__ __align__(256) __half g_ql[(size_t)BB*NH*SS*HD];
__device__ __align__(256) __half g_kh[(size_t)BB*NKV*SS*HD];
__device__ __align__(256) __half g_vh[(size_t)BB*NKV*SS*HD];

// ------------------------- PTX helpers --------------------------------------
__device__ __forceinline__ uint32_t smem_u32(const void* p) {
    uint32_t a;
    asm("{ .reg .u64 t; cvta.to.shared.u64 t, %1; cvt.u32.u64 %0, t; }" : "=r"(a) : "l"(p));
    return a;
}
__device__ __forceinline__ uint32_t h2u(__half2 v) {
    return *reinterpret_cast<uint32_t*>(&v);
}
__device__ __forceinline__ void cp_async16(uint32_t saddr, const void* gaddr) {
    asm volatile("cp.async.cg.shared.global [%0], [%1], 16;" :: "r"(saddr), "l"(gaddr) : "memory");
}
__device__ __forceinline__ void cp_commit() {
    asm volatile("cp.async.commit_group;" ::: "memory");
}
__device__ __forceinline__ void cp_wait_1() {
    asm volatile("cp.async.wait_group 1;" ::: "memory");
}
__device__ __forceinline__ void ldsm4(uint32_t* r, uint32_t addr) {
    asm volatile("ldmatrix.sync.aligned.m8n8.x4.shared.b16 {%0,%1,%2,%3}, [%4];"
                 : "=r"(r[0]), "=r"(r[1]), "=r"(r[2]), "=r"(r[3]) : "r"(addr));
}
__device__ __forceinline__ void ldsm4t(uint32_t* r, uint32_t addr) {
    asm volatile("ldmatrix.sync.aligned.m8n8.x4.trans.shared.b16 {%0,%1,%2,%3}, [%4];"
                 : "=r"(r[0]), "=r"(r[1]), "=r"(r[2]), "=r"(r[3]) : "r"(addr));
}
__device__ __forceinline__ void mma16816h(float* c, const uint32_t* a, uint32_t b0, uint32_t b1) {
    asm volatile(
        "mma.sync.aligned.m16n8k16.row.col.f32.f16.f16.f32 "
        "{%0,%1,%2,%3}, {%4,%5,%6,%7}, {%8,%9}, {%0,%1,%2,%3};"
        : "+f"(c[0]), "+f"(c[1]), "+f"(c[2]), "+f"(c[3])
        : "r"(a[0]), "r"(a[1]), "r"(a[2]), "r"(a[3]), "r"(b0), "r"(b1));
}
#define SWZ(off) ((off) ^ (((off) >> 3) & 0x70))

__device__ __forceinline__ uint32_t tile_off(int row, int d) {
    uint32_t off = (uint32_t)(row * 128 + (d & 63) * 2);
    return (uint32_t)((d >> 6) * 8192) + SWZ(off);
}

// ------------------------- prep kernels -------------------------------------
__global__ __launch_bounds__(256) void conv_half(
    const float* __restrict__ X, __half* __restrict__ Y, int n)
{
    int t = blockIdx.x * blockDim.x + threadIdx.x;
    if (t < n) Y[t] = __float2half(X[t]);
}
__global__ __launch_bounds__(256) void transp_h(
    const float* __restrict__ W, __half* __restrict__ Y, int K, int N)
{
    __shared__ float t[32][33];
    int k0 = blockIdx.y * 32, n0 = blockIdx.x * 32;
    int tx = threadIdx.x & 31, ty = threadIdx.x >> 5;
#pragma unroll
    for (int i = 0; i < 4; i++)
        t[ty + i * 8][tx] = W[(size_t)(k0 + ty + i * 8) * N + n0 + tx];
    __syncthreads();
#pragma unroll
    for (int i = 0; i < 4; i++) {
        int n = n0 + ty + i * 8;
        int k = k0 + tx;
        Y[(size_t)n * K + k] = __float2half(t[tx][ty + i * 8]);
    }
}

// ------------------------- HMMA GEMM (fp16 operands) ------------------------
// Single-sync multistage pipeline (NST=3, prologue fills 2 stages), 2 CTAs/SM.
__global__ __launch_bounds__(256, 2) void gemm_tc(
    const __half* __restrict__ A2, const __half* __restrict__ B2,
    float* __restrict__ Cq, float* __restrict__ Ck, __half* __restrict__ Cv,
    int K2, int mode, int ldN)
{
    extern __shared__ char dsm[];
    const int tid = threadIdx.x;
    const int wid = tid >> 5;
    const int lane = tid & 31;
    const int m0 = blockIdx.y * 128;
    const int n0 = blockIdx.x * 128;
    const int warpM = (wid & 3) * 32;
    const int warpN = (wid >> 2) * 64;

    uint32_t raw = smem_u32(dsm);
    uint32_t sbase = (raw + 1023u) & ~1023u;
    char* dtile = dsm + (sbase - raw);

    const int nk = K2 >> 6;
    const int colb = (tid & 7) * 16;
    const int r0 = tid >> 3;

    float c[2][8][4];
#pragma unroll
    for (int mi = 0; mi < 2; mi++)
#pragma unroll
        for (int nf = 0; nf < 8; nf++)
#pragma unroll
            for (int j = 0; j < 4; j++) c[mi][nf][j] = 0.f;

    const int lrow = lane & 15;
    const int lchunk = (lane >> 4) * 16;

    // prologue: fill NST-1 = 2 stages
#pragma unroll
    for (int s = 0; s < NST - 1; s++) {
        uint32_t sA = sbase + s * STAGE_BYTES;
        uint32_t sB = sA + 16384;
        int k0 = s * 64;
#pragma unroll
        for (int i = 0; i < 4; i++) {
            int row = i * 32 + r0;
            uint32_t so = SWZ((uint32_t)(row * 128 + colb));
            cp_async16(sA + so, A2 + (size_t)(m0 + row) * K2 + k0 + (tid & 7) * 8);
            cp_async16(sB + so, B2 + (size_t)(n0 + row) * K2 + k0 + (tid & 7) * 8);
        }
        cp_commit();
    }

    for (int ck = 0; ck < nk; ck++) {
        const int s = ck - (ck / NST) * NST;
        cp_wait_1();           // group for chunk ck complete
        __syncthreads();       // data visible + prev reads of freed stage done

        // prefetch chunk ck+2 into the stage freed last iteration
        const int nck = ck + NST - 1;
        if (nck < nk) {
            const int ps = nck - (nck / NST) * NST;
            uint32_t pA = sbase + ps * STAGE_BYTES;
            uint32_t pB = pA + 16384;
            int k0 = nck * 64;
#pragma unroll
            for (int i = 0; i < 4; i++) {
                int row = i * 32 + r0;
                uint32_t so = SWZ((uint32_t)(row * 128 + colb));
                cp_async16(pA + so, A2 + (size_t)(m0 + row) * K2 + k0 + (tid & 7) * 8);
                cp_async16(pB + so, B2 + (size_t)(n0 + row) * K2 + k0 + (tid & 7) * 8);
            }
        }
        cp_commit();           // commit (possibly empty) group every iter

        uint32_t sA = sbase + s * STAGE_BYTES;
        uint32_t sB = sA + 16384;
#pragma unroll
        for (int ks = 0; ks < 4; ks++) {
            const int kb = ks * 32 + lchunk;
            uint32_t a[2][4], b[4][4];
#pragma unroll
            for (int mi = 0; mi < 2; mi++) {
                int row = warpM + mi * 16 + lrow;
                ldsm4(a[mi], sA + SWZ((uint32_t)(row * 128 + kb)));
            }
#pragma unroll
            for (int ni = 0; ni < 4; ni++) {
                int row = warpN + ni * 16 + lrow;
                ldsm4(b[ni], sB + SWZ((uint32_t)(row * 128 + kb)));
            }
#pragma unroll
            for (int mi = 0; mi < 2; mi++)
#pragma unroll
                for (int ni = 0; ni < 4; ni++) {
                    mma16816h(c[mi][2 * ni + 0], a[mi], b[ni][0], b[ni][2]);
                    mma16816h(c[mi][2 * ni + 1], a[mi], b[ni][1], b[ni][3]);
                }
        }
    }

    __syncthreads();
    float* stile = (float*)dtile;
    {
        int rquad = lane >> 2;
        int cpair = (lane & 3) << 1;
#pragma unroll
        for (int mi = 0; mi < 2; mi++) {
            int rbase = warpM + mi * 16 + rquad;
#pragma unroll
            for (int nf = 0; nf < 8; nf++) {
                int col = warpN + nf * 8 + cpair;
                *(float2*)&stile[rbase * 132 + col]       = make_float2(c[mi][nf][0], c[mi][nf][1]);
                *(float2*)&stile[(rbase + 8) * 132 + col] = make_float2(c[mi][nf][2], c[mi][nf][3]);
            }
        }
    }
    __syncthreads();

    if (mode == 0) {
#pragma unroll
        for (int i = 0; i < 16; i++) {
            int idx = i * 256 + tid;
            int row = idx >> 5, c4 = idx & 31;
            float4 v = *(float4*)&stile[row * 132 + c4 * 4];
            int m = m0 + row;
            *(float4*)&Cq[(size_t)m * ldN + n0 + c4 * 4] = v;
        }
    } else if (n0 < 3072) {
        float* tens; int hh, hp;
        if (n0 < 2048) { tens = Cq; hh = n0 >> 8;          hp = NH; }
        else           { tens = Ck; hh = (n0 - 2048) >> 8; hp = NKV; }
        int d0 = n0 & 255;
#pragma unroll
        for (int i = 0; i < 16; i++) {
            int idx = i * 256 + tid;
            int row = idx >> 5, c4 = idx & 31;
            float4 v = *(float4*)&stile[row * 132 + c4 * 4];
            int m = m0 + row;
            int b = m >> 11, sq = m & (SS - 1);
            *(float4*)&tens[(((size_t)(b * hp + hh)) * SS + sq) * HD + d0 + c4 * 4] = v;
        }
    } else {
        int hh = (n0 - 3072) >> 8;
        int d0 = n0 & 255;
#pragma unroll
        for (int i = 0; i < 16; i++) {
            int idx = i * 256 + tid;
            int row = idx >> 5, c4 = idx & 31;
            float4 v = *(float4*)&stile[row * 132 + c4 * 4];
            int m = m0 + row;
            int b = m >> 11, sq = m & (SS - 1);
            __half* dst = Cv + (((size_t)(b * NKV + hh)) * SS + sq) * HD + d0 + c4 * 4;
            *(__half2*)&dst[0] = __floats2half2_rn(v.x, v.y);
            *(__half2*)&dst[2] = __floats2half2_rn(v.z, v.w);
        }
    }
}

// --------------- RoPE + fp16 conversions ------------------------------------
__global__ __launch_bounds__(256) void rope_split_h(
    const float* __restrict__ X, __half* __restrict__ Xh, __half* __restrict__ Xl,
    const int* __restrict__ pos_ids, int heads, float scale)
{
    int t = blockIdx.x * blockDim.x + threadIdx.x;
    int d = t & 127;
    int s = (t >> 7) & (SS - 1);
    int rest = t >> 18;
    int hh = rest % heads;
    int b  = rest / heads;
    if (b >= BB) return;
    float p = (float)pos_ids[b * SS + s];
    float inv = powf(10000.f, -(float)d * (1.f / 128.f));
    float ang = p * inv;
    float si, co;
    sincosf(ang, &si, &co);
    size_t base = (((size_t)b * heads + hh) * SS + s) * HD;
    float x1 = X[base + d], x2 = X[base + d + 128];
    float r1 = (x1 * co - x2 * si) * scale;
    float r2 = (x2 * co + x1 * si) * scale;
    __half h1 = __float2half(r1), h2 = __float2half(r2);
    Xh[base + d] = h1;       Xh[base + d + 128] = h2;
    Xl[base + d] = __float2half(r1 - __half2float(h1));
    Xl[base + d + 128] = __float2half(r2 - __half2float(h2));
}
__global__ __launch_bounds__(256) void rope_h(
    const float* __restrict__ X, __half* __restrict__ Xh,
    const int* __restrict__ pos_ids, int heads)
{
    int t = blockIdx.x * blockDim.x + threadIdx.x;
    int d = t & 127;
    int s = (t >> 7) & (SS - 1);
    int rest = t >> 18;
    int hh = rest % heads;
    int b  = rest / heads;
    if (b >= BB) return;
    float p = (float)pos_ids[b * SS + s];
    float inv = powf(10000.f, -(float)d * (1.f / 128.f));
    float ang = p * inv;
    float si, co;
    sincosf(ang, &si, &co);
    size_t base = (((size_t)b * heads + hh) * SS + s) * HD;
    float x1 = X[base + d], x2 = X[base + d + 128];
    Xh[base + d]       = __float2half(x1 * co - x2 * si);
    Xh[base + d + 128] = __float2half(x2 * co + x1 * si);
}

// ------------------------- tensor-core flash attention ----------------------
__device__ __forceinline__ void cp_att_wait1() {
    asm volatile("cp.async.wait_group 1;" ::: "memory");
}
__device__ __forceinline__ void load_tile_async(uint32_t sdst, const __half* g, int tid) {
#pragma unroll
    for (int i = 0; i < 16; i++) {
        int idx = i * 128 + tid;
        int row = idx >> 5;
        int d = (idx & 31) * 8;
        cp_async16(sdst + tile_off(row, d), g + row * HD + d);
    }
}

__global__ __launch_bounds__(128) void attn_tc(
    const __half* __restrict__ Qh, const __half* __restrict__ Ql,
    const __half* __restrict__ Kh, const __half* __restrict__ Vh,
    __half* __restrict__ A2O)
{
    extern __shared__ char dsm[];
    uint32_t raw = smem_u32(dsm);
    uint32_t sb = (raw + 1023u) & ~1023u;
    const uint32_t sQh = sb, sQl = sb + 32768, sKh = sb + 65536, sVh = sb + 98304;

    const int tid = threadIdx.x;
    const int wid = tid >> 5;
    const int lane = tid & 31;
    const int qblk = blockIdx.x;
    const int h = blockIdx.y;
    const int b = blockIdx.z;
    const int kv = h >> 1;
    const int warpM = wid * 16;

    const __half* qhp = Qh + (((size_t)(b * NH + h)) * SS + qblk * 64) * HD;
    const __half* qlp = Ql + (((size_t)(b * NH + h)) * SS + qblk * 64) * HD;
    const __half* khp = Kh + ((size_t)(b * NKV + kv)) * SS * HD;
    const __half* vhp = Vh + ((size_t)(b * NKV + kv)) * SS * HD;

    int lo = qblk * 64 - (WIN - 1);
    if (lo < 0) lo = 0;
    lo &= ~63;
    const int hi = qblk * 64;

    load_tile_async(sQh, qhp, tid);
    load_tile_async(sQl, qlp, tid);
    load_tile_async(sKh, khp + (size_t)lo * HD, tid);
    cp_commit();
    load_tile_async(sVh, vhp + (size_t)lo * HD, tid);
    cp_commit();

    float oacc[32][4];
#pragma unroll
    for (int i = 0; i < 32; i++)
#pragma unroll
        for (int j = 0; j < 4; j++) oacc[i][j] = 0.f;
    float m0 = -1e30f, m1 = -1e30f, l0 = 0.f, l1 = 0.f;

    const int lrow = lane & 15;
    const int lhalf = (lane >> 4) * 16;
    const int qi = qblk * 64 + warpM + (lane >> 2);

    for (int kt = lo; kt <= hi; kt += 64) {
        cp_att_wait1();
        __syncthreads();

        float sacc[8][4];
#pragma unroll
        for (int i = 0; i < 8; i++)
#pragma unroll
            for (int j = 0; j < 4; j++) sacc[i][j] = 0.f;

#pragma unroll
        for (int kc = 0; kc < 16; kc++) {
            const int c = kc >> 2;
            const int colb = (kc & 3) * 32 + lhalf;
            uint32_t aqh[4], aql[4];
            uint32_t aoff = (uint32_t)(c * 8192) + SWZ((uint32_t)((warpM + lrow) * 128 + colb));
            ldsm4(aqh, sQh + aoff);
            ldsm4(aql, sQl + aoff);
#pragma unroll
            for (int g = 0; g < 4; g++) {
                uint32_t boff = (uint32_t)(c * 8192) + SWZ((uint32_t)((g * 16 + lrow) * 128 + colb));
                uint32_t bh[4];
                ldsm4(bh, sKh + boff);
                mma16816h(sacc[2 * g],     aqh, bh[0], bh[2]);
                mma16816h(sacc[2 * g + 1], aqh, bh[1], bh[3]);
                mma16816h(sacc[2 * g],     aql, bh[0], bh[2]);
                mma16816h(sacc[2 * g + 1], aql, bh[1], bh[3]);
            }
        }
        __syncthreads();
        if (kt + 64 <= hi)
            load_tile_async(sKh, khp + (size_t)(kt + 64) * HD, tid);
        cp_commit();

        float tm0 = -1e30f, tm1 = -1e30f;
#pragma unroll
        for (int nt = 0; nt < 8; nt++) {
#pragma unroll
            for (int j = 0; j < 4; j++) {
                int kj = kt + nt * 8 + (lane & 3) * 2 + (j & 1);
                int row = qi + ((j >> 1) * 8);
                float x = sacc[nt][j];
                float e = __expf(2.f * x);
                float s = 50.f * __fdividef(e - 1.f, e + 1.f);
                bool ok = (kj <= row) && (row - kj < WIN);
                s = ok ? s : -1e30f;
                sacc[nt][j] = s;
                if (j < 2) tm0 = fmaxf(tm0, s); else tm1 = fmaxf(tm1, s);
            }
        }
        tm0 = fmaxf(tm0, __shfl_xor_sync(0xffffffffu, tm0, 1));
        tm0 = fmaxf(tm0, __shfl_xor_sync(0xffffffffu, tm0, 2));
        tm1 = fmaxf(tm1, __shfl_xor_sync(0xffffffffu, tm1, 1));
        tm1 = fmaxf(tm1, __shfl_xor_sync(0xffffffffu, tm1, 2));

        float mn0 = fmaxf(m0, tm0), mn1 = fmaxf(m1, tm1);
        float al0 = __expf(m0 - mn0), al1 = __expf(m1 - mn1);
        m0 = mn0; m1 = mn1;

        float rs0 = 0.f, rs1 = 0.f;
#pragma unroll
        for (int nt = 0; nt < 8; nt++) {
            float p0 = __expf(sacc[nt][0] - mn0);
            float p1 = __expf(sacc[nt][1] - mn0);
            float p2 = __expf(sacc[nt][2] - mn1);
            float p3 = __expf(sacc[nt][3] - mn1);
            sacc[nt][0] = p0; sacc[nt][1] = p1; sacc[nt][2] = p2; sacc[nt][3] = p3;
            rs0 += p0 + p1; rs1 += p2 + p3;
        }
        rs0 += __shfl_xor_sync(0xffffffffu, rs0, 1);
        rs0 += __shfl_xor_sync(0xffffffffu, rs0, 2);
        rs1 += __shfl_xor_sync(0xffffffffu, rs1, 1);
        rs1 += __shfl_xor_sync(0xffffffffu, rs1, 2);
        l0 = l0 * al0 + rs0;
        l1 = l1 * al1 + rs1;

        uint32_t aP[4][4];
#pragma unroll
        for (int kc2 = 0; kc2 < 4; kc2++) {
            aP[kc2][0] = h2u(__floats2half2_rn(sacc[2 * kc2][0],     sacc[2 * kc2][1]));
            aP[kc2][1] = h2u(__floats2half2_rn(sacc[2 * kc2][2],     sacc[2 * kc2][3]));
            aP[kc2][2] = h2u(__floats2half2_rn(sacc[2 * kc2 + 1][0], sacc[2 * kc2 + 1][1]));
            aP[kc2][3] = h2u(__floats2half2_rn(sacc[2 * kc2 + 1][2], sacc[2 * kc2 + 1][3]));
        }

#pragma unroll
        for (int dt = 0; dt < 32; dt++) {
            oacc[dt][0] *= al0; oacc[dt][1] *= al0;
            oacc[dt][2] *= al1; oacc[dt][3] *= al1;
        }

        cp_att_wait1();
        __syncthreads();

#pragma unroll
        for (int kc2 = 0; kc2 < 4; kc2++) {
#pragma unroll
            for (int dg = 0; dg < 16; dg++) {
                int key = kc2 * 16 + lrow;
                int d = dg * 16 + (lane >> 4) * 8;
                uint32_t r[4];
                ldsm4t(r, sVh + tile_off(key, d));
                mma16816h(oacc[dg * 2],     aP[kc2], r[0], r[1]);
                mma16816h(oacc[dg * 2 + 1], aP[kc2], r[2], r[3]);
            }
        }
        __syncthreads();
        if (kt + 64 <= hi)
            load_tile_async(sVh, vhp + (size_t)(kt + 64) * HD, tid);
        cp_commit();
    }

    float il0 = __fdividef(1.f, l0);
    float il1 = __fdividef(1.f, l1);
    __half* a0 = A2O + ((size_t)(b * SS + qi)) * KO + h * HD;
    __half* a1 = A2O + ((size_t)(b * SS + qi + 8)) * KO + h * HD;
    int cbase = (lane & 3) * 2;
#pragma unroll
    for (int dt = 0; dt < 32; dt++) {
        int col = dt * 8 + cbase;
        *(__half2*)&a0[col] = __floats2half2_rn(oacc[dt][0] * il0, oacc[dt][1] * il0);
        *(__half2*)&a1[col] = __floats2half2_rn(oacc[dt][2] * il1, oacc[dt][3] * il1);
    }
}

// ---------------------------------------------------------------------------
extern "C" void kernel_launch(void* const* d_in, const int* in_sizes, int n_in,
                              void* d_out, int out_size)
{
    const float* hid = (const float*)d_in[0];
    const int*   pos = (const int*)d_in[2];
    const float* Wq  = (const float*)d_in[3];
    const float* Wk  = (const float*)d_in[4];
    const float* Wv  = (const float*)d_in[5];
    const float* Wo  = (const float*)d_in[6];
    float* out = (float*)d_out;

    float *qp, *kp;
    __half *a2, *b2, *a2o, *b2o, *qh_, *ql_, *kh_, *vh_;
    cudaGetSymbolAddress((void**)&qp,  g_q);
    cudaGetSymbolAddress((void**)&kp,  g_k);
    cudaGetSymbolAddress((void**)&a2,  g_a2);
    cudaGetSymbolAddress((void**)&b2,  g_b2);
    cudaGetSymbolAddress((void**)&a2o, g_a2o);
    cudaGetSymbolAddress((void**)&b2o, g_b2o);
    cudaGetSymbolAddress((void**)&qh_, g_qh);
    cudaGetSymbolAddress((void**)&ql_, g_ql);
    cudaGetSymbolAddress((void**)&kh_, g_kh);
    cudaGetSymbolAddress((void**)&vh_, g_vh);

    cudaFuncSetAttribute(gemm_tc, cudaFuncAttributeMaxDynamicSharedMemorySize, GEMM_SMEM);
    cudaFuncSetAttribute(attn_tc, cudaFuncAttributeMaxDynamicSharedMemorySize, ATT_SMEM);

    // ---- QKV projections: plain fp16 A, fp16 W, K=2304 ----
    conv_half<<<(MROWS*HH + 255)/256, 256>>>(hid, a2, MROWS*HH);
    transp_h<<<dim3(2048/32, HH/32), 256>>>(Wq, b2, HH, 2048);
    transp_h<<<dim3(1024/32, HH/32), 256>>>(Wk, b2 + (size_t)2048*HH, HH, 1024);
    transp_h<<<dim3(1024/32, HH/32), 256>>>(Wv, b2 + (size_t)3072*HH, HH, 1024);
    gemm_tc<<<dim3(NQKV/128, MROWS/128), 256, GEMM_SMEM>>>(a2, b2, qp, kp, vh_, HH, 1, 0);

    // ---- RoPE + fp16 conversions ----
    rope_split_h<<<(BB*NH*SS*128)/256, 256>>>(qp, qh_, ql_, pos, NH, 1.f/(16.f*50.f));
    rope_h<<<(BB*NKV*SS*128)/256, 256>>>(kp, kh_, pos, NKV);

    // ---- flash attention (fp16 HMMA) ----
    attn_tc<<<dim3(SS/64, NH, BB), 128, ATT_SMEM>>>(qh_, ql_, kh_, vh_, a2o);

    // ---- out projection (plain fp16, K=2048) ----
    transp_h<<<dim3(HH/32, 2048/32), 256>>>(Wo, b2o, 2048, HH);
    gemm_tc<<<dim3(HH/128, MROWS/128), 256, GEMM_SMEM>>>(a2o, b2o, out, nullptr, nullptr, KO, 0, HH);
}

// round 11
// speedup vs baseline: 8.8517x; 1.0705x over previous
#include <cuda_runtime.h>
#include <cuda_fp16.h>
#include <cstdint>
#include <math.h>

#define BB   2
#define SS   2048
#define HH   2304
#define NH   8
#define HD   256
#define NKV  4
#define WIN  512
#define MROWS (BB*SS)            // 4096
#define KO   2048                // O-proj K (plain fp16)
#define NQKV (NH*HD + 2*NKV*HD)  // 4096
#define NST   3
#define STAGE_BYTES 32768
#define GEMM_SMEM (NST*STAGE_BYTES + 1024)
#define ATT_SMEM (3*32768 + 1024)   // Qh Kh Vh tiles (32KB each) + align

// ------------------------- device scratch (no allocs allowed) ---------------
__device__ float g_q[(size_t)BB*NH*SS*HD];
__device__ float g_k[(size_t)BB*NKV*SS*HD];
__device__ __align__(256) __half g_a2 [(size_t)MROWS*HH];
__device__ __align__(256) __half g_b2 [(size_t)NQKV*HH];
__device__ __align__(256) __half g_a2o[(size_t)MROWS*KO];
__device__ __align__(256) __half g_b2o[(size_t)HH*KO];
__device__ __align__(256) __half g_qh[(size_t)BB*NH*SS*HD];
__device__ __align__(256) __half g_kh[(size_t)BB*NKV*SS*HD];
__device__ __align__(256) __half g_vh[(size_t)BB*NKV*SS*HD];

// ------------------------- PTX helpers --------------------------------------
__device__ __forceinline__ uint32_t smem_u32(const void* p) {
    uint32_t a;
    asm("{ .reg .u64 t; cvta.to.shared.u64 t, %1; cvt.u32.u64 %0, t; }" : "=r"(a) : "l"(p));
    return a;
}
__device__ __forceinline__ uint32_t h2u(__half2 v) {
    return *reinterpret_cast<uint32_t*>(&v);
}
__device__ __forceinline__ void cp_async16(uint32_t saddr, const void* gaddr) {
    asm volatile("cp.async.cg.shared.global [%0], [%1], 16;" :: "r"(saddr), "l"(gaddr) : "memory");
}
__device__ __forceinline__ void cp_commit() {
    asm volatile("cp.async.commit_group;" ::: "memory");
}
__device__ __forceinline__ void cp_wait_1() {
    asm volatile("cp.async.wait_group 1;" ::: "memory");
}
__device__ __forceinline__ void ldsm4(uint32_t* r, uint32_t addr) {
    asm volatile("ldmatrix.sync.aligned.m8n8.x4.shared.b16 {%0,%1,%2,%3}, [%4];"
                 : "=r"(r[0]), "=r"(r[1]), "=r"(r[2]), "=r"(r[3]) : "r"(addr));
}
__device__ __forceinline__ void ldsm4t(uint32_t* r, uint32_t addr) {
    asm volatile("ldmatrix.sync.aligned.m8n8.x4.trans.shared.b16 {%0,%1,%2,%3}, [%4];"
                 : "=r"(r[0]), "=r"(r[1]), "=r"(r[2]), "=r"(r[3]) : "r"(addr));
}
__device__ __forceinline__ void mma16816h(float* c, const uint32_t* a, uint32_t b0, uint32_t b1) {
    asm volatile(
        "mma.sync.aligned.m16n8k16.row.col.f32.f16.f16.f32 "
        "{%0,%1,%2,%3}, {%4,%5,%6,%7}, {%8,%9}, {%0,%1,%2,%3};"
        : "+f"(c[0]), "+f"(c[1]), "+f"(c[2]), "+f"(c[3])
        : "r"(a[0]), "r"(a[1]), "r"(a[2]), "r"(a[3]), "r"(b0), "r"(b1));
}
#define SWZ(off) ((off) ^ (((off) >> 3) & 0x70))

__device__ __forceinline__ uint32_t tile_off(int row, int d) {
    uint32_t off = (uint32_t)(row * 128 + (d & 63) * 2);
    return (uint32_t)((d >> 6) * 8192) + SWZ(off);
}

// ------------------------- prep kernels -------------------------------------
__global__ __launch_bounds__(256) void conv_half(
    const float* __restrict__ X, __half* __restrict__ Y, int n)
{
    int t = blockIdx.x * blockDim.x + threadIdx.x;
    if (t < n) Y[t] = __float2half(X[t]);
}
__global__ __launch_bounds__(256) void transp_h(
    const float* __restrict__ W, __half* __restrict__ Y, int K, int N)
{
    __shared__ float t[32][33];
    int k0 = blockIdx.y * 32, n0 = blockIdx.x * 32;
    int tx = threadIdx.x & 31, ty = threadIdx.x >> 5;
#pragma unroll
    for (int i = 0; i < 4; i++)
        t[ty + i * 8][tx] = W[(size_t)(k0 + ty + i * 8) * N + n0 + tx];
    __syncthreads();
#pragma unroll
    for (int i = 0; i < 4; i++) {
        int n = n0 + ty + i * 8;
        int k = k0 + tx;
        Y[(size_t)n * K + k] = __float2half(t[tx][ty + i * 8]);
    }
}

// ------------------------- HMMA GEMM (fp16 operands) ------------------------
__global__ __launch_bounds__(256, 2) void gemm_tc(
    const __half* __restrict__ A2, const __half* __restrict__ B2,
    float* __restrict__ Cq, float* __restrict__ Ck, __half* __restrict__ Cv,
    int K2, int mode, int ldN)
{
    extern __shared__ char dsm[];
    const int tid = threadIdx.x;
    const int wid = tid >> 5;
    const int lane = tid & 31;
    const int m0 = blockIdx.y * 128;
    const int n0 = blockIdx.x * 128;
    const int warpM = (wid & 3) * 32;
    const int warpN = (wid >> 2) * 64;

    uint32_t raw = smem_u32(dsm);
    uint32_t sbase = (raw + 1023u) & ~1023u;
    char* dtile = dsm + (sbase - raw);

    const int nk = K2 >> 6;
    const int colb = (tid & 7) * 16;
    const int r0 = tid >> 3;

    float c[2][8][4];
#pragma unroll
    for (int mi = 0; mi < 2; mi++)
#pragma unroll
        for (int nf = 0; nf < 8; nf++)
#pragma unroll
            for (int j = 0; j < 4; j++) c[mi][nf][j] = 0.f;

    const int lrow = lane & 15;
    const int lchunk = (lane >> 4) * 16;

#pragma unroll
    for (int s = 0; s < NST - 1; s++) {
        uint32_t sA = sbase + s * STAGE_BYTES;
        uint32_t sB = sA + 16384;
        int k0 = s * 64;
#pragma unroll
        for (int i = 0; i < 4; i++) {
            int row = i * 32 + r0;
            uint32_t so = SWZ((uint32_t)(row * 128 + colb));
            cp_async16(sA + so, A2 + (size_t)(m0 + row) * K2 + k0 + (tid & 7) * 8);
            cp_async16(sB + so, B2 + (size_t)(n0 + row) * K2 + k0 + (tid & 7) * 8);
        }
        cp_commit();
    }

    for (int ck = 0; ck < nk; ck++) {
        const int s = ck - (ck / NST) * NST;
        cp_wait_1();
        __syncthreads();

        const int nck = ck + NST - 1;
        if (nck < nk) {
            const int ps = nck - (nck / NST) * NST;
            uint32_t pA = sbase + ps * STAGE_BYTES;
            uint32_t pB = pA + 16384;
            int k0 = nck * 64;
#pragma unroll
            for (int i = 0; i < 4; i++) {
                int row = i * 32 + r0;
                uint32_t so = SWZ((uint32_t)(row * 128 + colb));
                cp_async16(pA + so, A2 + (size_t)(m0 + row) * K2 + k0 + (tid & 7) * 8);
                cp_async16(pB + so, B2 + (size_t)(n0 + row) * K2 + k0 + (tid & 7) * 8);
            }
        }
        cp_commit();

        uint32_t sA = sbase + s * STAGE_BYTES;
        uint32_t sB = sA + 16384;
#pragma unroll
        for (int ks = 0; ks < 4; ks++) {
            const int kb = ks * 32 + lchunk;
            uint32_t a[2][4], b[4][4];
#pragma unroll
            for (int mi = 0; mi < 2; mi++) {
                int row = warpM + mi * 16 + lrow;
                ldsm4(a[mi], sA + SWZ((uint32_t)(row * 128 + kb)));
            }
#pragma unroll
            for (int ni = 0; ni < 4; ni++) {
                int row = warpN + ni * 16 + lrow;
                ldsm4(b[ni], sB + SWZ((uint32_t)(row * 128 + kb)));
            }
#pragma unroll
            for (int mi = 0; mi < 2; mi++)
#pragma unroll
                for (int ni = 0; ni < 4; ni++) {
                    mma16816h(c[mi][2 * ni + 0], a[mi], b[ni][0], b[ni][2]);
                    mma16816h(c[mi][2 * ni + 1], a[mi], b[ni][1], b[ni][3]);
                }
        }
    }

    __syncthreads();
    float* stile = (float*)dtile;
    {
        int rquad = lane >> 2;
        int cpair = (lane & 3) << 1;
#pragma unroll
        for (int mi = 0; mi < 2; mi++) {
            int rbase = warpM + mi * 16 + rquad;
#pragma unroll
            for (int nf = 0; nf < 8; nf++) {
                int col = warpN + nf * 8 + cpair;
                *(float2*)&stile[rbase * 132 + col]       = make_float2(c[mi][nf][0], c[mi][nf][1]);
                *(float2*)&stile[(rbase + 8) * 132 + col] = make_float2(c[mi][nf][2], c[mi][nf][3]);
            }
        }
    }
    __syncthreads();

    if (mode == 0) {
#pragma unroll
        for (int i = 0; i < 16; i++) {
            int idx = i * 256 + tid;
            int row = idx >> 5, c4 = idx & 31;
            float4 v = *(float4*)&stile[row * 132 + c4 * 4];
            int m = m0 + row;
            *(float4*)&Cq[(size_t)m * ldN + n0 + c4 * 4] = v;
        }
    } else if (n0 < 3072) {
        float* tens; int hh, hp;
        if (n0 < 2048) { tens = Cq; hh = n0 >> 8;          hp = NH; }
        else           { tens = Ck; hh = (n0 - 2048) >> 8; hp = NKV; }
        int d0 = n0 & 255;
#pragma unroll
        for (int i = 0; i < 16; i++) {
            int idx = i * 256 + tid;
            int row = idx >> 5, c4 = idx & 31;
            float4 v = *(float4*)&stile[row * 132 + c4 * 4];
            int m = m0 + row;
            int b = m >> 11, sq = m & (SS - 1);
            *(float4*)&tens[(((size_t)(b * hp + hh)) * SS + sq) * HD + d0 + c4 * 4] = v;
        }
    } else {
        int hh = (n0 - 3072) >> 8;
        int d0 = n0 & 255;
#pragma unroll
        for (int i = 0; i < 16; i++) {
            int idx = i * 256 + tid;
            int row = idx >> 5, c4 = idx & 31;
            float4 v = *(float4*)&stile[row * 132 + c4 * 4];
            int m = m0 + row;
            int b = m >> 11, sq = m & (SS - 1);
            __half* dst = Cv + (((size_t)(b * NKV + hh)) * SS + sq) * HD + d0 + c4 * 4;
            *(__half2*)&dst[0] = __floats2half2_rn(v.x, v.y);
            *(__half2*)&dst[2] = __floats2half2_rn(v.z, v.w);
        }
    }
}

// --------------- RoPE + fp16 conversion (scaled) -----------------------------
__global__ __launch_bounds__(256) void rope_h(
    const float* __restrict__ X, __half* __restrict__ Xh,
    const int* __restrict__ pos_ids, int heads, float scale)
{
    int t = blockIdx.x * blockDim.x + threadIdx.x;
    int d = t & 127;
    int s = (t >> 7) & (SS - 1);
    int rest = t >> 18;
    int hh = rest % heads;
    int b  = rest / heads;
    if (b >= BB) return;
    float p = (float)pos_ids[b * SS + s];
    float inv = powf(10000.f, -(float)d * (1.f / 128.f));
    float ang = p * inv;
    float si, co;
    sincosf(ang, &si, &co);
    size_t base = (((size_t)b * heads + hh) * SS + s) * HD;
    float x1 = X[base + d], x2 = X[base + d + 128];
    Xh[base + d]       = __float2half((x1 * co - x2 * si) * scale);
    Xh[base + d + 128] = __float2half((x2 * co + x1 * si) * scale);
}

// ------------------------- tensor-core flash attention ----------------------
__device__ __forceinline__ void cp_att_wait1() {
    asm volatile("cp.async.wait_group 1;" ::: "memory");
}
__device__ __forceinline__ void load_tile_async(uint32_t sdst, const __half* g, int tid) {
#pragma unroll
    for (int i = 0; i < 16; i++) {
        int idx = i * 128 + tid;
        int row = idx >> 5;
        int d = (idx & 31) * 8;
        cp_async16(sdst + tile_off(row, d), g + row * HD + d);
    }
}

__global__ __launch_bounds__(128, 2) void attn_tc(
    const __half* __restrict__ Qh,
    const __half* __restrict__ Kh, const __half* __restrict__ Vh,
    __half* __restrict__ A2O)
{
    extern __shared__ char dsm[];
    uint32_t raw = smem_u32(dsm);
    uint32_t sb = (raw + 1023u) & ~1023u;
    const uint32_t sQh = sb, sKh = sb + 32768, sVh = sb + 65536;

    const int tid = threadIdx.x;
    const int wid = tid >> 5;
    const int lane = tid & 31;
    const int qblk = blockIdx.x;
    const int h = blockIdx.y;
    const int b = blockIdx.z;
    const int kv = h >> 1;
    const int warpM = wid * 16;

    const __half* qhp = Qh + (((size_t)(b * NH + h)) * SS + qblk * 64) * HD;
    const __half* khp = Kh + ((size_t)(b * NKV + kv)) * SS * HD;
    const __half* vhp = Vh + ((size_t)(b * NKV + kv)) * SS * HD;

    int lo = qblk * 64 - (WIN - 1);
    if (lo < 0) lo = 0;
    lo &= ~63;
    const int hi = qblk * 64;

    load_tile_async(sQh, qhp, tid);
    load_tile_async(sKh, khp + (size_t)lo * HD, tid);
    cp_commit();
    load_tile_async(sVh, vhp + (size_t)lo * HD, tid);
    cp_commit();

    float oacc[32][4];
#pragma unroll
    for (int i = 0; i < 32; i++)
#pragma unroll
        for (int j = 0; j < 4; j++) oacc[i][j] = 0.f;
    float m0 = -1e30f, m1 = -1e30f, l0 = 0.f, l1 = 0.f;

    const int lrow = lane & 15;
    const int lhalf = (lane >> 4) * 16;
    const int qi = qblk * 64 + warpM + (lane >> 2);

    for (int kt = lo; kt <= hi; kt += 64) {
        cp_att_wait1();
        __syncthreads();

        float sacc[8][4];
#pragma unroll
        for (int i = 0; i < 8; i++)
#pragma unroll
            for (int j = 0; j < 4; j++) sacc[i][j] = 0.f;

#pragma unroll
        for (int kc = 0; kc < 16; kc++) {
            const int c = kc >> 2;
            const int colb = (kc & 3) * 32 + lhalf;
            uint32_t aqh[4];
            uint32_t aoff = (uint32_t)(c * 8192) + SWZ((uint32_t)((warpM + lrow) * 128 + colb));
            ldsm4(aqh, sQh + aoff);
#pragma unroll
            for (int g = 0; g < 4; g++) {
                uint32_t boff = (uint32_t)(c * 8192) + SWZ((uint32_t)((g * 16 + lrow) * 128 + colb));
                uint32_t bh[4];
                ldsm4(bh, sKh + boff);
                mma16816h(sacc[2 * g],     aqh, bh[0], bh[2]);
                mma16816h(sacc[2 * g + 1], aqh, bh[1], bh[3]);
            }
        }
        __syncthreads();
        if (kt + 64 <= hi)
            load_tile_async(sKh, khp + (size_t)(kt + 64) * HD, tid);
        cp_commit();

        float tm0 = -1e30f, tm1 = -1e30f;
#pragma unroll
        for (int nt = 0; nt < 8; nt++) {
#pragma unroll
            for (int j = 0; j < 4; j++) {
                int kj = kt + nt * 8 + (lane & 3) * 2 + (j & 1);
                int row = qi + ((j >> 1) * 8);
                float x = sacc[nt][j];
                float e = __expf(2.f * x);
                float s = 50.f * __fdividef(e - 1.f, e + 1.f);
                bool ok = (kj <= row) && (row - kj < WIN);
                s = ok ? s : -1e30f;
                sacc[nt][j] = s;
                if (j < 2) tm0 = fmaxf(tm0, s); else tm1 = fmaxf(tm1, s);
            }
        }
        tm0 = fmaxf(tm0, __shfl_xor_sync(0xffffffffu, tm0, 1));
        tm0 = fmaxf(tm0, __shfl_xor_sync(0xffffffffu, tm0, 2));
        tm1 = fmaxf(tm1, __shfl_xor_sync(0xffffffffu, tm1, 1));
        tm1 = fmaxf(tm1, __shfl_xor_sync(0xffffffffu, tm1, 2));

        float mn0 = fmaxf(m0, tm0), mn1 = fmaxf(m1, tm1);
        float al0 = __expf(m0 - mn0), al1 = __expf(m1 - mn1);
        m0 = mn0; m1 = mn1;

        float rs0 = 0.f, rs1 = 0.f;
#pragma unroll
        for (int nt = 0; nt < 8; nt++) {
            float p0 = __expf(sacc[nt][0] - mn0);
            float p1 = __expf(sacc[nt][1] - mn0);
            float p2 = __expf(sacc[nt][2] - mn1);
            float p3 = __expf(sacc[nt][3] - mn1);
            sacc[nt][0] = p0; sacc[nt][1] = p1; sacc[nt][2] = p2; sacc[nt][3] = p3;
            rs0 += p0 + p1; rs1 += p2 + p3;
        }
        rs0 += __shfl_xor_sync(0xffffffffu, rs0, 1);
        rs0 += __shfl_xor_sync(0xffffffffu, rs0, 2);
        rs1 += __shfl_xor_sync(0xffffffffu, rs1, 1);
        rs1 += __shfl_xor_sync(0xffffffffu, rs1, 2);
        l0 = l0 * al0 + rs0;
        l1 = l1 * al1 + rs1;

        uint32_t aP[4][4];
#pragma unroll
        for (int kc2 = 0; kc2 < 4; kc2++) {
            aP[kc2][0] = h2u(__floats2half2_rn(sacc[2 * kc2][0],     sacc[2 * kc2][1]));
            aP[kc2][1] = h2u(__floats2half2_rn(sacc[2 * kc2][2],     sacc[2 * kc2][3]));
            aP[kc2][2] = h2u(__floats2half2_rn(sacc[2 * kc2 + 1][0], sacc[2 * kc2 + 1][1]));
            aP[kc2][3] = h2u(__floats2half2_rn(sacc[2 * kc2 + 1][2], sacc[2 * kc2 + 1][3]));
        }

#pragma unroll
        for (int dt = 0; dt < 32; dt++) {
            oacc[dt][0] *= al0; oacc[dt][1] *= al0;
            oacc[dt][2] *= al1; oacc[dt][3] *= al1;
        }

        cp_att_wait1();
        __syncthreads();

#pragma unroll
        for (int kc2 = 0; kc2 < 4; kc2++) {
#pragma unroll
            for (int dg = 0; dg < 16; dg++) {
                int key = kc2 * 16 + lrow;
                int d = dg * 16 + (lane >> 4) * 8;
                uint32_t r[4];
                ldsm4t(r, sVh + tile_off(key, d));
                mma16816h(oacc[dg * 2],     aP[kc2], r[0], r[1]);
                mma16816h(oacc[dg * 2 + 1], aP[kc2], r[2], r[3]);
            }
        }
        __syncthreads();
        if (kt + 64 <= hi)
            load_tile_async(sVh, vhp + (size_t)(kt + 64) * HD, tid);
        cp_commit();
    }

    float il0 = __fdividef(1.f, l0);
    float il1 = __fdividef(1.f, l1);
    __half* a0 = A2O + ((size_t)(b * SS + qi)) * KO + h * HD;
    __half* a1 = A2O + ((size_t)(b * SS + qi + 8)) * KO + h * HD;
    int cbase = (lane & 3) * 2;
#pragma unroll
    for (int dt = 0; dt < 32; dt++) {
        int col = dt * 8 + cbase;
        *(__half2*)&a0[col] = __floats2half2_rn(oacc[dt][0] * il0, oacc[dt][1] * il0);
        *(__half2*)&a1[col] = __floats2half2_rn(oacc[dt][2] * il1, oacc[dt][3] * il1);
    }
}

// ---------------------------------------------------------------------------
extern "C" void kernel_launch(void* const* d_in, const int* in_sizes, int n_in,
                              void* d_out, int out_size)
{
    const float* hid = (const float*)d_in[0];
    const int*   pos = (const int*)d_in[2];
    const float* Wq  = (const float*)d_in[3];
    const float* Wk  = (const float*)d_in[4];
    const float* Wv  = (const float*)d_in[5];
    const float* Wo  = (const float*)d_in[6];
    float* out = (float*)d_out;

    float *qp, *kp;
    __half *a2, *b2, *a2o, *b2o, *qh_, *kh_, *vh_;
    cudaGetSymbolAddress((void**)&qp,  g_q);
    cudaGetSymbolAddress((void**)&kp,  g_k);
    cudaGetSymbolAddress((void**)&a2,  g_a2);
    cudaGetSymbolAddress((void**)&b2,  g_b2);
    cudaGetSymbolAddress((void**)&a2o, g_a2o);
    cudaGetSymbolAddress((void**)&b2o, g_b2o);
    cudaGetSymbolAddress((void**)&qh_, g_qh);
    cudaGetSymbolAddress((void**)&kh_, g_kh);
    cudaGetSymbolAddress((void**)&vh_, g_vh);

    cudaFuncSetAttribute(gemm_tc, cudaFuncAttributeMaxDynamicSharedMemorySize, GEMM_SMEM);
    cudaFuncSetAttribute(attn_tc, cudaFuncAttributeMaxDynamicSharedMemorySize, ATT_SMEM);

    // ---- QKV projections: plain fp16 A, fp16 W, K=2304 ----
    conv_half<<<(MROWS*HH + 255)/256, 256>>>(hid, a2, MROWS*HH);
    transp_h<<<dim3(2048/32, HH/32), 256>>>(Wq, b2, HH, 2048);
    transp_h<<<dim3(1024/32, HH/32), 256>>>(Wk, b2 + (size_t)2048*HH, HH, 1024);
    transp_h<<<dim3(1024/32, HH/32), 256>>>(Wv, b2 + (size_t)3072*HH, HH, 1024);
    gemm_tc<<<dim3(NQKV/128, MROWS/128), 256, GEMM_SMEM>>>(a2, b2, qp, kp, vh_, HH, 1, 0);

    // ---- RoPE + fp16 conversions ----
    rope_h<<<(BB*NH*SS*128)/256, 256>>>(qp, qh_, pos, NH, 1.f/(16.f*50.f));
    rope_h<<<(BB*NKV*SS*128)/256, 256>>>(kp, kh_, pos, NKV, 1.f);

    // ---- flash attention (fp16 HMMA, single-pass QK, 2 CTA/SM) ----
    attn_tc<<<dim3(SS/64, NH, BB), 128, ATT_SMEM>>>(qh_, kh_, vh_, a2o);

    // ---- out projection (plain fp16, K=2048) ----
    transp_h<<<dim3(HH/32, 2048/32), 256>>>(Wo, b2o, 2048, HH);
    gemm_tc<<<dim3(HH/128, MROWS/128), 256, GEMM_SMEM>>>(a2o, b2o, out, nullptr, nullptr, KO, 0, HH);
}